// round 1
// baseline (speedup 1.0000x reference)
#include <cuda_runtime.h>

#define SLEN    2048
#define DMODEL  1024
#define NHEAD   16
#define DKH     64
#define NB      4
#define MTOT    (NB * SLEN)     // 8192

// ---------------- scratch (allocation-free: __device__ globals) ----------------
__device__ float g_Q[(size_t)NB * NHEAD * SLEN * DKH];   // [B,H,S,64]
__device__ float g_K[(size_t)NB * NHEAD * SLEN * DKH];
__device__ float g_V[(size_t)NB * NHEAD * SLEN * DKH];
__device__ float g_AO[(size_t)MTOT * DMODEL];            // [B*S, H*64]

// ---------------- SGEMM mainloop: C[64,64] tile of X[M,K] @ W[N,K]^T ----------
#define PA 33   // A smem pitch (scalar reads, conflict-free stores)
#define PW 68   // W^T smem pitch (16B-aligned float4 reads, d-major)

__device__ __forceinline__ void gemm_mainloop(const float* __restrict__ X,
                                              const float* __restrict__ W,
                                              int m0, int n0, int tid,
                                              float* As, float* Wt, float* acc) {
    const int ty = tid >> 4;       // 0..15 -> 4 M rows
    const int tx = tid & 15;       // 0..15 -> 4 N cols
#pragma unroll 1
    for (int kb = 0; kb < DMODEL; kb += 32) {
        __syncthreads();
#pragma unroll
        for (int j = 0; j < 2; j++) {
            int i   = tid + j * 256;          // 0..511 float4 slots
            int row = i >> 3;                 // 0..63
            int kq  = (i & 7) << 2;           // 0,4,..,28
            float4 a = *(const float4*)(X + (size_t)(m0 + row) * DMODEL + kb + kq);
            As[row * PA + kq + 0] = a.x;
            As[row * PA + kq + 1] = a.y;
            As[row * PA + kq + 2] = a.z;
            As[row * PA + kq + 3] = a.w;
            float4 w = *(const float4*)(W + (size_t)(n0 + row) * DMODEL + kb + kq);
            Wt[(kq + 0) * PW + row] = w.x;
            Wt[(kq + 1) * PW + row] = w.y;
            Wt[(kq + 2) * PW + row] = w.z;
            Wt[(kq + 3) * PW + row] = w.w;
        }
        __syncthreads();
#pragma unroll
        for (int k = 0; k < 32; k++) {
            float a0 = As[(ty * 4 + 0) * PA + k];
            float a1 = As[(ty * 4 + 1) * PA + k];
            float a2 = As[(ty * 4 + 2) * PA + k];
            float a3 = As[(ty * 4 + 3) * PA + k];
            float4 b = *(const float4*)(Wt + k * PW + tx * 4);
            acc[0]  += a0 * b.x;  acc[1]  += a0 * b.y;  acc[2]  += a0 * b.z;  acc[3]  += a0 * b.w;
            acc[4]  += a1 * b.x;  acc[5]  += a1 * b.y;  acc[6]  += a1 * b.z;  acc[7]  += a1 * b.w;
            acc[8]  += a2 * b.x;  acc[9]  += a2 * b.y;  acc[10] += a2 * b.z;  acc[11] += a2 * b.w;
            acc[12] += a3 * b.x;  acc[13] += a3 * b.y;  acc[14] += a3 * b.z;  acc[15] += a3 * b.w;
        }
    }
}

// ---------------- QKV projection (z selects Q/K/V), head-split output ---------
__global__ __launch_bounds__(256) void proj_kernel(
    const float* __restrict__ xq, const float* __restrict__ xk, const float* __restrict__ xv,
    const float* __restrict__ wq, const float* __restrict__ wk, const float* __restrict__ wv,
    const float* __restrict__ bq, const float* __restrict__ bk, const float* __restrict__ bv)
{
    __shared__ float As[64 * PA];
    __shared__ float Wt[32 * PW];
    const int z = blockIdx.z;
    const float* X  = (z == 0) ? xq : (z == 1) ? xk : xv;
    const float* W  = (z == 0) ? wq : (z == 1) ? wk : wv;
    const float* Bb = (z == 0) ? bq : (z == 1) ? bk : bv;
    float* Out      = (z == 0) ? g_Q : (z == 1) ? g_K : g_V;

    const int m0 = blockIdx.y * 64, n0 = blockIdx.x * 64;
    const int tid = threadIdx.x;
    float acc[16];
#pragma unroll
    for (int i = 0; i < 16; i++) acc[i] = 0.f;

    gemm_mainloop(X, W, m0, n0, tid, As, Wt, acc);

    const int ty = tid >> 4, tx = tid & 15;
    const int n  = n0 + tx * 4;
    const int hh = n >> 6, dd = n & 63;      // n..n+3 stay inside one head
    float4 bv4 = *(const float4*)(Bb + n);
#pragma unroll
    for (int u = 0; u < 4; u++) {
        int m  = m0 + ty * 4 + u;
        int bb = m >> 11;                    // m / 2048
        int ss = m & (SLEN - 1);
        float4 r;
        r.x = acc[u * 4 + 0] + bv4.x;
        r.y = acc[u * 4 + 1] + bv4.y;
        r.z = acc[u * 4 + 2] + bv4.z;
        r.w = acc[u * 4 + 3] + bv4.w;
        *(float4*)(Out + (((size_t)bb * NHEAD + hh) * SLEN + ss) * DKH + dd) = r;
    }
}

// ---------------- Flash attention (causal), fp32 ------------------------------
#define PQ 65
#define PK 68
#define PP 68
#define ATTN_SMEM_FLOATS (64 * PQ + 64 * PK + 64 * 64 + 64 * PP)
#define ATTN_SMEM_BYTES  (ATTN_SMEM_FLOATS * 4)

__global__ __launch_bounds__(256) void attn_kernel() {
    extern __shared__ float sm[];
    float* Qs = sm;                 // [64][65]  Q[r][d]
    float* Kt = Qs + 64 * PQ;       // [64][68]  K^T[d][c]
    float* Vs = Kt + 64 * PK;       // [64][64]  V[c][d]
    float* Ps = Vs + 64 * 64;       // [64][68]  P[r][c]

    const int qb = blockIdx.x;      // query tile 0..31
    const int bh = blockIdx.y;      // 0..63
    const size_t base = (size_t)bh * SLEN * DKH;
    const float* Qh = g_Q + base;
    const float* Kh = g_K + base;
    const float* Vh = g_V + base;

    const int tid = threadIdx.x;
    const int r  = tid >> 2;        // row 0..63
    const int cg = tid & 3;         // column group: cols cg*16..cg*16+15
    const int qi = qb * 64 + r;

    // load Q tile
#pragma unroll
    for (int j = 0; j < 4; j++) {
        int i   = tid + j * 256;
        int row = i >> 4;
        int dq  = (i & 15) << 2;
        float4 v = *(const float4*)(Qh + (size_t)(qb * 64 + row) * DKH + dq);
        Qs[row * PQ + dq + 0] = v.x;
        Qs[row * PQ + dq + 1] = v.y;
        Qs[row * PQ + dq + 2] = v.z;
        Qs[row * PQ + dq + 3] = v.w;
    }

    float o[16];
#pragma unroll
    for (int j = 0; j < 16; j++) o[j] = 0.f;
    float m_run = -3.0e38f, l_run = 0.f;

    for (int kb = 0; kb <= qb; kb++) {
        __syncthreads();   // prior-iteration smem reads done
#pragma unroll
        for (int j = 0; j < 4; j++) {
            int i   = tid + j * 256;
            int row = i >> 4;
            int dq  = (i & 15) << 2;
            float4 kv = *(const float4*)(Kh + (size_t)(kb * 64 + row) * DKH + dq);
            Kt[(dq + 0) * PK + row] = kv.x;
            Kt[(dq + 1) * PK + row] = kv.y;
            Kt[(dq + 2) * PK + row] = kv.z;
            Kt[(dq + 3) * PK + row] = kv.w;
            float4 vv = *(const float4*)(Vh + (size_t)(kb * 64 + row) * DKH + dq);
            *(float4*)(Vs + row * 64 + dq) = vv;
        }
        __syncthreads();

        // S = Q K^T for this thread's (row r, 16 cols)
        float s[16];
#pragma unroll
        for (int j = 0; j < 16; j++) s[j] = 0.f;
#pragma unroll 8
        for (int d = 0; d < 64; d++) {
            float qv = Qs[r * PQ + d];
            const float* kr = Kt + d * PK + cg * 16;
            float4 k0 = *(const float4*)(kr + 0);
            float4 k1 = *(const float4*)(kr + 4);
            float4 k2 = *(const float4*)(kr + 8);
            float4 k3 = *(const float4*)(kr + 12);
            s[0]  += qv * k0.x; s[1]  += qv * k0.y; s[2]  += qv * k0.z; s[3]  += qv * k0.w;
            s[4]  += qv * k1.x; s[5]  += qv * k1.y; s[6]  += qv * k1.z; s[7]  += qv * k1.w;
            s[8]  += qv * k2.x; s[9]  += qv * k2.y; s[10] += qv * k2.z; s[11] += qv * k2.w;
            s[12] += qv * k3.x; s[13] += qv * k3.y; s[14] += qv * k3.z; s[15] += qv * k3.w;
        }
#pragma unroll
        for (int j = 0; j < 16; j++) s[j] *= 0.125f;   // 1/sqrt(64)
        if (kb == qb) {
#pragma unroll
            for (int j = 0; j < 16; j++) {
                int kj = kb * 64 + cg * 16 + j;
                if (kj > qi) s[j] = -1.0e30f;
            }
        }

        // online softmax (row = 4 consecutive lanes)
        float mx = s[0];
#pragma unroll
        for (int j = 1; j < 16; j++) mx = fmaxf(mx, s[j]);
        mx = fmaxf(mx, __shfl_xor_sync(0xffffffffu, mx, 1));
        mx = fmaxf(mx, __shfl_xor_sync(0xffffffffu, mx, 2));
        float m_new = fmaxf(m_run, mx);
        float corr  = __expf(m_run - m_new);
        float rs = 0.f;
#pragma unroll
        for (int j = 0; j < 16; j++) { s[j] = __expf(s[j] - m_new); rs += s[j]; }
        rs += __shfl_xor_sync(0xffffffffu, rs, 1);
        rs += __shfl_xor_sync(0xffffffffu, rs, 2);
        l_run = l_run * corr + rs;
        m_run = m_new;
#pragma unroll
        for (int j = 0; j < 16; j++) o[j] *= corr;

        // stage P to smem for the PV product
#pragma unroll
        for (int j = 0; j < 4; j++)
            *(float4*)(Ps + r * PP + cg * 16 + j * 4) =
                make_float4(s[j*4+0], s[j*4+1], s[j*4+2], s[j*4+3]);
        __syncthreads();

        // O += P V : thread owns (row r, d-slice cg*16..+15)
#pragma unroll 8
        for (int c = 0; c < 64; c++) {
            float p = Ps[r * PP + c];
            const float* vr = Vs + c * 64 + cg * 16;
            float4 v0 = *(const float4*)(vr + 0);
            float4 v1 = *(const float4*)(vr + 4);
            float4 v2 = *(const float4*)(vr + 8);
            float4 v3 = *(const float4*)(vr + 12);
            o[0]  += p * v0.x; o[1]  += p * v0.y; o[2]  += p * v0.z; o[3]  += p * v0.w;
            o[4]  += p * v1.x; o[5]  += p * v1.y; o[6]  += p * v1.z; o[7]  += p * v1.w;
            o[8]  += p * v2.x; o[9]  += p * v2.y; o[10] += p * v2.z; o[11] += p * v2.w;
            o[12] += p * v3.x; o[13] += p * v3.y; o[14] += p * v3.z; o[15] += p * v3.w;
        }
    }

    const float inv = 1.0f / l_run;
    const int bb = bh >> 4, hh = bh & 15;
    float* dst = g_AO + ((size_t)bb * SLEN + qi) * DMODEL + hh * DKH + cg * 16;
#pragma unroll
    for (int j = 0; j < 4; j++)
        *(float4*)(dst + j * 4) =
            make_float4(o[j*4+0]*inv, o[j*4+1]*inv, o[j*4+2]*inv, o[j*4+3]*inv);
}

// ---------------- output projection -------------------------------------------
__global__ __launch_bounds__(256) void outproj_kernel(const float* __restrict__ W,
                                                      const float* __restrict__ Bb,
                                                      float* __restrict__ Out) {
    __shared__ float As[64 * PA];
    __shared__ float Wt[32 * PW];
    const int m0 = blockIdx.y * 64, n0 = blockIdx.x * 64;
    const int tid = threadIdx.x;
    float acc[16];
#pragma unroll
    for (int i = 0; i < 16; i++) acc[i] = 0.f;

    gemm_mainloop(g_AO, W, m0, n0, tid, As, Wt, acc);

    const int ty = tid >> 4, tx = tid & 15;
    const int n  = n0 + tx * 4;
    float4 bv4 = *(const float4*)(Bb + n);
#pragma unroll
    for (int u = 0; u < 4; u++) {
        int m = m0 + ty * 4 + u;
        float4 r;
        r.x = acc[u * 4 + 0] + bv4.x;
        r.y = acc[u * 4 + 1] + bv4.y;
        r.z = acc[u * 4 + 2] + bv4.z;
        r.w = acc[u * 4 + 3] + bv4.w;
        *(float4*)(Out + (size_t)m * DMODEL + n) = r;
    }
}

// ---------------- launch -------------------------------------------------------
extern "C" void kernel_launch(void* const* d_in, const int* in_sizes, int n_in,
                              void* d_out, int out_size) {
    const float* q  = (const float*)d_in[0];
    const float* k  = (const float*)d_in[1];
    const float* v  = (const float*)d_in[2];
    // d_in[3] = mask (int32 tril) — causal, applied analytically
    const float* wq = (const float*)d_in[4];
    const float* bq = (const float*)d_in[5];
    const float* wk = (const float*)d_in[6];
    const float* bk = (const float*)d_in[7];
    const float* wv = (const float*)d_in[8];
    const float* bv = (const float*)d_in[9];
    const float* wo = (const float*)d_in[10];
    const float* bo = (const float*)d_in[11];
    float* out = (float*)d_out;

    proj_kernel<<<dim3(DMODEL / 64, MTOT / 64, 3), 256>>>(q, k, v, wq, wk, wv, bq, bk, bv);

    cudaFuncSetAttribute(attn_kernel, cudaFuncAttributeMaxDynamicSharedMemorySize,
                         ATTN_SMEM_BYTES);
    attn_kernel<<<dim3(SLEN / 64, NB * NHEAD), 256, ATTN_SMEM_BYTES>>>();

    outproj_kernel<<<dim3(DMODEL / 64, MTOT / 64), 256>>>(wo, bo, out);
}

// round 3
// speedup vs baseline: 1.2393x; 1.2393x over previous
#include <cuda_runtime.h>
#include <cstdint>

#define SLEN    2048
#define DMODEL  1024
#define NHEAD   16
#define DKH     64
#define NB      4
#define MTOT    (NB * SLEN)     // 8192

// ---------------- scratch (allocation-free: __device__ globals) ----------------
__device__ float g_Q[(size_t)NB * NHEAD * SLEN * DKH];   // [B,H,S,64]
__device__ float g_K[(size_t)NB * NHEAD * SLEN * DKH];
__device__ float g_V[(size_t)NB * NHEAD * SLEN * DKH];
__device__ float g_AO[(size_t)MTOT * DMODEL];            // [B*S, H*64]

// ======================= tf32 tensor-core GEMM =================================
// C[M,N] = X[M,K] @ W[N,K]^T + bias   (both operands K-contiguous -> row.col NT)
#define BM 128
#define BN 128
#define BK 16
#define GPITCH 20                     // floats; multiple of 4 (cp.async 16B), conflict-free
#define GSTAGES 4
#define TILEF (BM * GPITCH)           // floats per operand per stage
#define GEMM_SMEM (GSTAGES * TILEF * 2 * 4)   // 81920 bytes

__device__ __forceinline__ uint32_t f2tf32(float f) {
    uint32_t u;
    asm("cvt.rna.tf32.f32 %0, %1;" : "=r"(u) : "f"(f));
    return u;
}

__device__ __forceinline__ void mma_tf32(float c[4], const uint32_t a[4], const uint32_t b[2]) {
    asm volatile(
        "mma.sync.aligned.m16n8k8.row.col.f32.tf32.tf32.f32 "
        "{%0,%1,%2,%3}, {%4,%5,%6,%7}, {%8,%9}, {%0,%1,%2,%3};"
        : "+f"(c[0]), "+f"(c[1]), "+f"(c[2]), "+f"(c[3])
        : "r"(a[0]), "r"(a[1]), "r"(a[2]), "r"(a[3]), "r"(b[0]), "r"(b[1]));
}

__device__ __forceinline__ uint32_t smem_u32(const void* p) {
    uint32_t a;
    asm("{ .reg .u64 t; cvta.to.shared.u64 t, %1; cvt.u32.u64 %0, t; }" : "=r"(a) : "l"(p));
    return a;
}

__device__ __forceinline__ void cp16(uint32_t dst, const void* src) {
    asm volatile("cp.async.cg.shared.global [%0], [%1], 16;" :: "r"(dst), "l"(src));
}
#define CP_COMMIT() asm volatile("cp.async.commit_group;")
#define CP_WAIT(n)  asm volatile("cp.async.wait_group %0;" :: "n"(n))

// 8 warps as 2(m) x 4(n); warp tile 64x32 = 4x4 frags of m16n8k8.
__device__ __forceinline__ void gemm_tf32_main(const float* __restrict__ X,
                                               const float* __restrict__ W,
                                               int m0, int n0,
                                               float acc[4][4][4]) {
    extern __shared__ float sm[];
    float* As = sm;
    float* Bs = sm + GSTAGES * TILEF;

    const int tid  = threadIdx.x;
    const int lane = tid & 31, warp = tid >> 5;
    const int wm = warp >> 2, wn = warp & 3;
    const int g  = lane >> 2, tg = lane & 3;

    const uint32_t aAddr = smem_u32(As);
    const uint32_t bAddr = smem_u32(Bs);

    const int lrow = tid >> 2;            // 0..63
    const int lcol = (tid & 3) << 2;      // 0,4,8,12

    const float* xg0 = X + (size_t)(m0 + lrow) * DMODEL + lcol;
    const float* wg0 = W + (size_t)(n0 + lrow) * DMODEL + lcol;
    const uint32_t so0 = (uint32_t)(lrow * GPITCH + lcol) << 2;
    const uint32_t so1 = (uint32_t)((lrow + 64) * GPITCH + lcol) << 2;

#define ISSUE_TILE(kt)                                                              \
    do {                                                                            \
        int _s = (kt) % GSTAGES;                                                    \
        uint32_t _ab = aAddr + ((uint32_t)(_s * TILEF) << 2);                       \
        uint32_t _bb = bAddr + ((uint32_t)(_s * TILEF) << 2);                       \
        const float* _x = xg0 + (size_t)(kt) * BK;                                  \
        const float* _w = wg0 + (size_t)(kt) * BK;                                  \
        cp16(_ab + so0, _x);                                                        \
        cp16(_ab + so1, _x + (size_t)64 * DMODEL);                                  \
        cp16(_bb + so0, _w);                                                        \
        cp16(_bb + so1, _w + (size_t)64 * DMODEL);                                  \
    } while (0)

    const int NT = DMODEL / BK;   // 64
    ISSUE_TILE(0); CP_COMMIT();
    ISSUE_TILE(1); CP_COMMIT();
    ISSUE_TILE(2); CP_COMMIT();

    for (int kt = 0; kt < NT; kt++) {
        CP_WAIT(2);
        __syncthreads();
        if (kt + 3 < NT) ISSUE_TILE(kt + 3);
        CP_COMMIT();

        const int s = kt % GSTAGES;
        const float* Asb = As + s * TILEF;
        const float* Bsb = Bs + s * TILEF;
#pragma unroll
        for (int kk = 0; kk < BK; kk += 8) {
            uint32_t a[4][4], b[4][2];
#pragma unroll
            for (int fm = 0; fm < 4; fm++) {
                const float* p = Asb + (wm * 64 + fm * 16 + g) * GPITCH + kk + tg;
                a[fm][0] = f2tf32(p[0]);
                a[fm][1] = f2tf32(p[8 * GPITCH]);
                a[fm][2] = f2tf32(p[4]);
                a[fm][3] = f2tf32(p[8 * GPITCH + 4]);
            }
#pragma unroll
            for (int fn = 0; fn < 4; fn++) {
                const float* p = Bsb + (wn * 32 + fn * 8 + g) * GPITCH + kk + tg;
                b[fn][0] = f2tf32(p[0]);
                b[fn][1] = f2tf32(p[4]);
            }
#pragma unroll
            for (int fm = 0; fm < 4; fm++)
#pragma unroll
                for (int fn = 0; fn < 4; fn++)
                    mma_tf32(acc[fm][fn], a[fm], b[fn]);
        }
    }
#undef ISSUE_TILE
}

// ---------------- QKV projection, head-split output ---------------------------
__global__ __launch_bounds__(256, 2) void qkv_tf32_kernel(
    const float* __restrict__ q, const float* __restrict__ k, const float* __restrict__ v,
    const float* __restrict__ wq, const float* __restrict__ wk, const float* __restrict__ wv,
    const float* __restrict__ bq, const float* __restrict__ bk, const float* __restrict__ bv)
{
    const int z = blockIdx.z;
    const float* X  = (z == 0) ? q  : (z == 1) ? k  : v;
    const float* W  = (z == 0) ? wq : (z == 1) ? wk : wv;
    const float* Bb = (z == 0) ? bq : (z == 1) ? bk : bv;
    float* Out      = (z == 0) ? g_Q : (z == 1) ? g_K : g_V;

    const int m0 = blockIdx.y * BM, n0 = blockIdx.x * BN;
    float acc[4][4][4];
#pragma unroll
    for (int i = 0; i < 4; i++)
#pragma unroll
        for (int j = 0; j < 4; j++)
#pragma unroll
            for (int t = 0; t < 4; t++) acc[i][j][t] = 0.f;

    gemm_tf32_main(X, W, m0, n0, acc);

    const int tid  = threadIdx.x;
    const int lane = tid & 31, warp = tid >> 5;
    const int wm = warp >> 2, wn = warp & 3;
    const int g  = lane >> 2, tg = lane & 3;

#pragma unroll
    for (int fn = 0; fn < 4; fn++) {
        const int n  = n0 + wn * 32 + fn * 8 + 2 * tg;
        const int hh = n >> 6, dd = n & 63;
        const float b0 = Bb[n], b1 = Bb[n + 1];
#pragma unroll
        for (int fm = 0; fm < 4; fm++) {
#pragma unroll
            for (int half = 0; half < 2; half++) {
                const int m  = m0 + wm * 64 + fm * 16 + g + half * 8;
                const int bb = m >> 11;
                const int ss = m & (SLEN - 1);
                float* dst = Out + (((size_t)bb * NHEAD + hh) * SLEN + ss) * DKH + dd;
                *(float2*)dst = make_float2(acc[fm][fn][half * 2 + 0] + b0,
                                            acc[fm][fn][half * 2 + 1] + b1);
            }
        }
    }
}

// ---------------- output projection -------------------------------------------
__global__ __launch_bounds__(256, 2) void outproj_tf32_kernel(
    const float* __restrict__ W, const float* __restrict__ Bb, float* __restrict__ Out)
{
    const int m0 = blockIdx.y * BM, n0 = blockIdx.x * BN;
    float acc[4][4][4];
#pragma unroll
    for (int i = 0; i < 4; i++)
#pragma unroll
        for (int j = 0; j < 4; j++)
#pragma unroll
            for (int t = 0; t < 4; t++) acc[i][j][t] = 0.f;

    gemm_tf32_main(g_AO, W, m0, n0, acc);

    const int tid  = threadIdx.x;
    const int lane = tid & 31, warp = tid >> 5;
    const int wm = warp >> 2, wn = warp & 3;
    const int g  = lane >> 2, tg = lane & 3;

#pragma unroll
    for (int fn = 0; fn < 4; fn++) {
        const int n = n0 + wn * 32 + fn * 8 + 2 * tg;
        const float b0 = Bb[n], b1 = Bb[n + 1];
#pragma unroll
        for (int fm = 0; fm < 4; fm++) {
#pragma unroll
            for (int half = 0; half < 2; half++) {
                const int m = m0 + wm * 64 + fm * 16 + g + half * 8;
                *(float2*)(Out + (size_t)m * DMODEL + n) =
                    make_float2(acc[fm][fn][half * 2 + 0] + b0,
                                acc[fm][fn][half * 2 + 1] + b1);
            }
        }
    }
}

// ---------------- Flash attention (causal), fp32 (unchanged from R1) ----------
#define PQ 65
#define PK 68
#define PP 68
#define ATTN_SMEM_FLOATS (64 * PQ + 64 * PK + 64 * 64 + 64 * PP)
#define ATTN_SMEM_BYTES  (ATTN_SMEM_FLOATS * 4)

__global__ __launch_bounds__(256) void attn_kernel() {
    extern __shared__ float sm[];
    float* Qs = sm;                 // [64][65]
    float* Kt = Qs + 64 * PQ;       // [64][68]  K^T[d][c]
    float* Vs = Kt + 64 * PK;       // [64][64]
    float* Ps = Vs + 64 * 64;       // [64][68]

    const int qb = blockIdx.x;
    const int bh = blockIdx.y;
    const size_t base = (size_t)bh * SLEN * DKH;
    const float* Qh = g_Q + base;
    const float* Kh = g_K + base;
    const float* Vh = g_V + base;

    const int tid = threadIdx.x;
    const int r  = tid >> 2;
    const int cg = tid & 3;
    const int qi = qb * 64 + r;

#pragma unroll
    for (int j = 0; j < 4; j++) {
        int i   = tid + j * 256;
        int row = i >> 4;
        int dq  = (i & 15) << 2;
        float4 v = *(const float4*)(Qh + (size_t)(qb * 64 + row) * DKH + dq);
        Qs[row * PQ + dq + 0] = v.x;
        Qs[row * PQ + dq + 1] = v.y;
        Qs[row * PQ + dq + 2] = v.z;
        Qs[row * PQ + dq + 3] = v.w;
    }

    float o[16];
#pragma unroll
    for (int j = 0; j < 16; j++) o[j] = 0.f;
    float m_run = -3.0e38f, l_run = 0.f;

    for (int kb = 0; kb <= qb; kb++) {
        __syncthreads();
#pragma unroll
        for (int j = 0; j < 4; j++) {
            int i   = tid + j * 256;
            int row = i >> 4;
            int dq  = (i & 15) << 2;
            float4 kv = *(const float4*)(Kh + (size_t)(kb * 64 + row) * DKH + dq);
            Kt[(dq + 0) * PK + row] = kv.x;
            Kt[(dq + 1) * PK + row] = kv.y;
            Kt[(dq + 2) * PK + row] = kv.z;
            Kt[(dq + 3) * PK + row] = kv.w;
            float4 vv = *(const float4*)(Vh + (size_t)(kb * 64 + row) * DKH + dq);
            *(float4*)(Vs + row * 64 + dq) = vv;
        }
        __syncthreads();

        float s[16];
#pragma unroll
        for (int j = 0; j < 16; j++) s[j] = 0.f;
#pragma unroll 8
        for (int d = 0; d < 64; d++) {
            float qv = Qs[r * PQ + d];
            const float* kr = Kt + d * PK + cg * 16;
            float4 k0 = *(const float4*)(kr + 0);
            float4 k1 = *(const float4*)(kr + 4);
            float4 k2 = *(const float4*)(kr + 8);
            float4 k3 = *(const float4*)(kr + 12);
            s[0]  += qv * k0.x; s[1]  += qv * k0.y; s[2]  += qv * k0.z; s[3]  += qv * k0.w;
            s[4]  += qv * k1.x; s[5]  += qv * k1.y; s[6]  += qv * k1.z; s[7]  += qv * k1.w;
            s[8]  += qv * k2.x; s[9]  += qv * k2.y; s[10] += qv * k2.z; s[11] += qv * k2.w;
            s[12] += qv * k3.x; s[13] += qv * k3.y; s[14] += qv * k3.z; s[15] += qv * k3.w;
        }
#pragma unroll
        for (int j = 0; j < 16; j++) s[j] *= 0.125f;
        if (kb == qb) {
#pragma unroll
            for (int j = 0; j < 16; j++) {
                int kj = kb * 64 + cg * 16 + j;
                if (kj > qi) s[j] = -1.0e30f;
            }
        }

        float mx = s[0];
#pragma unroll
        for (int j = 1; j < 16; j++) mx = fmaxf(mx, s[j]);
        mx = fmaxf(mx, __shfl_xor_sync(0xffffffffu, mx, 1));
        mx = fmaxf(mx, __shfl_xor_sync(0xffffffffu, mx, 2));
        float m_new = fmaxf(m_run, mx);
        float corr  = __expf(m_run - m_new);
        float rs = 0.f;
#pragma unroll
        for (int j = 0; j < 16; j++) { s[j] = __expf(s[j] - m_new); rs += s[j]; }
        rs += __shfl_xor_sync(0xffffffffu, rs, 1);
        rs += __shfl_xor_sync(0xffffffffu, rs, 2);
        l_run = l_run * corr + rs;
        m_run = m_new;
#pragma unroll
        for (int j = 0; j < 16; j++) o[j] *= corr;

#pragma unroll
        for (int j = 0; j < 4; j++)
            *(float4*)(Ps + r * PP + cg * 16 + j * 4) =
                make_float4(s[j*4+0], s[j*4+1], s[j*4+2], s[j*4+3]);
        __syncthreads();

#pragma unroll 8
        for (int c = 0; c < 64; c++) {
            float p = Ps[r * PP + c];
            const float* vr = Vs + c * 64 + cg * 16;
            float4 v0 = *(const float4*)(vr + 0);
            float4 v1 = *(const float4*)(vr + 4);
            float4 v2 = *(const float4*)(vr + 8);
            float4 v3 = *(const float4*)(vr + 12);
            o[0]  += p * v0.x; o[1]  += p * v0.y; o[2]  += p * v0.z; o[3]  += p * v0.w;
            o[4]  += p * v1.x; o[5]  += p * v1.y; o[6]  += p * v1.z; o[7]  += p * v1.w;
            o[8]  += p * v2.x; o[9]  += p * v2.y; o[10] += p * v2.z; o[11] += p * v2.w;
            o[12] += p * v3.x; o[13] += p * v3.y; o[14] += p * v3.z; o[15] += p * v3.w;
        }
    }

    const float inv = 1.0f / l_run;
    const int bb = bh >> 4, hh = bh & 15;
    float* dst = g_AO + ((size_t)bb * SLEN + qi) * DMODEL + hh * DKH + cg * 16;
#pragma unroll
    for (int j = 0; j < 4; j++)
        *(float4*)(dst + j * 4) =
            make_float4(o[j*4+0]*inv, o[j*4+1]*inv, o[j*4+2]*inv, o[j*4+3]*inv);
}

// ---------------- launch -------------------------------------------------------
extern "C" void kernel_launch(void* const* d_in, const int* in_sizes, int n_in,
                              void* d_out, int out_size) {
    const float* q  = (const float*)d_in[0];
    const float* k  = (const float*)d_in[1];
    const float* v  = (const float*)d_in[2];
    // d_in[3] = mask (int32 tril) — causal, applied analytically
    const float* wq = (const float*)d_in[4];
    const float* bq = (const float*)d_in[5];
    const float* wk = (const float*)d_in[6];
    const float* bk = (const float*)d_in[7];
    const float* wv = (const float*)d_in[8];
    const float* bv = (const float*)d_in[9];
    const float* wo = (const float*)d_in[10];
    const float* bo = (const float*)d_in[11];
    float* out = (float*)d_out;

    cudaFuncSetAttribute(qkv_tf32_kernel, cudaFuncAttributeMaxDynamicSharedMemorySize, GEMM_SMEM);
    cudaFuncSetAttribute(outproj_tf32_kernel, cudaFuncAttributeMaxDynamicSharedMemorySize, GEMM_SMEM);
    cudaFuncSetAttribute(attn_kernel, cudaFuncAttributeMaxDynamicSharedMemorySize, ATTN_SMEM_BYTES);

    qkv_tf32_kernel<<<dim3(DMODEL / BN, MTOT / BM, 3), 256, GEMM_SMEM>>>(
        q, k, v, wq, wk, wv, bq, bk, bv);

    attn_kernel<<<dim3(SLEN / 64, NB * NHEAD), 256, ATTN_SMEM_BYTES>>>();

    outproj_tf32_kernel<<<dim3(DMODEL / BN, MTOT / BM), 256, GEMM_SMEM>>>(wo, bo, out);
}

// round 5
// speedup vs baseline: 6.1746x; 4.9823x over previous
#include <cuda_runtime.h>
#include <cuda_fp16.h>
#include <cstdint>

#define SLEN    2048
#define DMODEL  1024
#define NHEAD   16
#define DKH     64
#define NB      4
#define MTOT    (NB * SLEN)     // 8192

// ---------------- scratch (allocation-free: __device__ globals) ----------------
__device__ float g_Q[(size_t)NB * NHEAD * SLEN * DKH];   // [B,H,S,64]
__device__ float g_K[(size_t)NB * NHEAD * SLEN * DKH];
__device__ float g_V[(size_t)NB * NHEAD * SLEN * DKH];
__device__ float g_AO[(size_t)MTOT * DMODEL];            // [B*S, H*64]

// ======================= tf32 tensor-core GEMM (unchanged R2) ==================
#define BM 128
#define BN 128
#define BK 16
#define GPITCH 20
#define GSTAGES 4
#define TILEF (BM * GPITCH)
#define GEMM_SMEM (GSTAGES * TILEF * 2 * 4)

__device__ __forceinline__ uint32_t f2tf32(float f) {
    uint32_t u;
    asm("cvt.rna.tf32.f32 %0, %1;" : "=r"(u) : "f"(f));
    return u;
}

__device__ __forceinline__ void mma_tf32(float c[4], const uint32_t a[4], const uint32_t b[2]) {
    asm volatile(
        "mma.sync.aligned.m16n8k8.row.col.f32.tf32.tf32.f32 "
        "{%0,%1,%2,%3}, {%4,%5,%6,%7}, {%8,%9}, {%0,%1,%2,%3};"
        : "+f"(c[0]), "+f"(c[1]), "+f"(c[2]), "+f"(c[3])
        : "r"(a[0]), "r"(a[1]), "r"(a[2]), "r"(a[3]), "r"(b[0]), "r"(b[1]));
}

__device__ __forceinline__ uint32_t smem_u32(const void* p) {
    uint32_t a;
    asm("{ .reg .u64 t; cvta.to.shared.u64 t, %1; cvt.u32.u64 %0, t; }" : "=r"(a) : "l"(p));
    return a;
}

__device__ __forceinline__ void cp16(uint32_t dst, const void* src) {
    asm volatile("cp.async.cg.shared.global [%0], [%1], 16;" :: "r"(dst), "l"(src));
}
#define CP_COMMIT() asm volatile("cp.async.commit_group;")
#define CP_WAIT(n)  asm volatile("cp.async.wait_group %0;" :: "n"(n))

__device__ __forceinline__ void gemm_tf32_main(const float* __restrict__ X,
                                               const float* __restrict__ W,
                                               int m0, int n0,
                                               float acc[4][4][4]) {
    extern __shared__ float sm[];
    float* As = sm;
    float* Bs = sm + GSTAGES * TILEF;

    const int tid  = threadIdx.x;
    const int lane = tid & 31, warp = tid >> 5;
    const int wm = warp >> 2, wn = warp & 3;
    const int g  = lane >> 2, tg = lane & 3;

    const uint32_t aAddr = smem_u32(As);
    const uint32_t bAddr = smem_u32(Bs);

    const int lrow = tid >> 2;
    const int lcol = (tid & 3) << 2;

    const float* xg0 = X + (size_t)(m0 + lrow) * DMODEL + lcol;
    const float* wg0 = W + (size_t)(n0 + lrow) * DMODEL + lcol;
    const uint32_t so0 = (uint32_t)(lrow * GPITCH + lcol) << 2;
    const uint32_t so1 = (uint32_t)((lrow + 64) * GPITCH + lcol) << 2;

#define ISSUE_TILE(kt)                                                              \
    do {                                                                            \
        int _s = (kt) % GSTAGES;                                                    \
        uint32_t _ab = aAddr + ((uint32_t)(_s * TILEF) << 2);                       \
        uint32_t _bb = bAddr + ((uint32_t)(_s * TILEF) << 2);                       \
        const float* _x = xg0 + (size_t)(kt) * BK;                                  \
        const float* _w = wg0 + (size_t)(kt) * BK;                                  \
        cp16(_ab + so0, _x);                                                        \
        cp16(_ab + so1, _x + (size_t)64 * DMODEL);                                  \
        cp16(_bb + so0, _w);                                                        \
        cp16(_bb + so1, _w + (size_t)64 * DMODEL);                                  \
    } while (0)

    const int NT = DMODEL / BK;
    ISSUE_TILE(0); CP_COMMIT();
    ISSUE_TILE(1); CP_COMMIT();
    ISSUE_TILE(2); CP_COMMIT();

    for (int kt = 0; kt < NT; kt++) {
        CP_WAIT(2);
        __syncthreads();
        if (kt + 3 < NT) ISSUE_TILE(kt + 3);
        CP_COMMIT();

        const int s = kt % GSTAGES;
        const float* Asb = As + s * TILEF;
        const float* Bsb = Bs + s * TILEF;
#pragma unroll
        for (int kk = 0; kk < BK; kk += 8) {
            uint32_t a[4][4], b[4][2];
#pragma unroll
            for (int fm = 0; fm < 4; fm++) {
                const float* p = Asb + (wm * 64 + fm * 16 + g) * GPITCH + kk + tg;
                a[fm][0] = f2tf32(p[0]);
                a[fm][1] = f2tf32(p[8 * GPITCH]);
                a[fm][2] = f2tf32(p[4]);
                a[fm][3] = f2tf32(p[8 * GPITCH + 4]);
            }
#pragma unroll
            for (int fn = 0; fn < 4; fn++) {
                const float* p = Bsb + (wn * 32 + fn * 8 + g) * GPITCH + kk + tg;
                b[fn][0] = f2tf32(p[0]);
                b[fn][1] = f2tf32(p[4]);
            }
#pragma unroll
            for (int fm = 0; fm < 4; fm++)
#pragma unroll
                for (int fn = 0; fn < 4; fn++)
                    mma_tf32(acc[fm][fn], a[fm], b[fn]);
        }
    }
#undef ISSUE_TILE
}

__global__ __launch_bounds__(256, 2) void qkv_tf32_kernel(
    const float* __restrict__ q, const float* __restrict__ k, const float* __restrict__ v,
    const float* __restrict__ wq, const float* __restrict__ wk, const float* __restrict__ wv,
    const float* __restrict__ bq, const float* __restrict__ bk, const float* __restrict__ bv)
{
    const int z = blockIdx.z;
    const float* X  = (z == 0) ? q  : (z == 1) ? k  : v;
    const float* W  = (z == 0) ? wq : (z == 1) ? wk : wv;
    const float* Bb = (z == 0) ? bq : (z == 1) ? bk : bv;
    float* Out      = (z == 0) ? g_Q : (z == 1) ? g_K : g_V;

    const int m0 = blockIdx.y * BM, n0 = blockIdx.x * BN;
    float acc[4][4][4];
#pragma unroll
    for (int i = 0; i < 4; i++)
#pragma unroll
        for (int j = 0; j < 4; j++)
#pragma unroll
            for (int t = 0; t < 4; t++) acc[i][j][t] = 0.f;

    gemm_tf32_main(X, W, m0, n0, acc);

    const int tid  = threadIdx.x;
    const int lane = tid & 31, warp = tid >> 5;
    const int wm = warp >> 2, wn = warp & 3;
    const int g  = lane >> 2, tg = lane & 3;

#pragma unroll
    for (int fn = 0; fn < 4; fn++) {
        const int n  = n0 + wn * 32 + fn * 8 + 2 * tg;
        const int hh = n >> 6, dd = n & 63;
        const float b0 = Bb[n], b1 = Bb[n + 1];
#pragma unroll
        for (int fm = 0; fm < 4; fm++) {
#pragma unroll
            for (int half = 0; half < 2; half++) {
                const int m  = m0 + wm * 64 + fm * 16 + g + half * 8;
                const int bb = m >> 11;
                const int ss = m & (SLEN - 1);
                float* dst = Out + (((size_t)bb * NHEAD + hh) * SLEN + ss) * DKH + dd;
                *(float2*)dst = make_float2(acc[fm][fn][half * 2 + 0] + b0,
                                            acc[fm][fn][half * 2 + 1] + b1);
            }
        }
    }
}

__global__ __launch_bounds__(256, 2) void outproj_tf32_kernel(
    const float* __restrict__ W, const float* __restrict__ Bb, float* __restrict__ Out)
{
    const int m0 = blockIdx.y * BM, n0 = blockIdx.x * BN;
    float acc[4][4][4];
#pragma unroll
    for (int i = 0; i < 4; i++)
#pragma unroll
        for (int j = 0; j < 4; j++)
#pragma unroll
            for (int t = 0; t < 4; t++) acc[i][j][t] = 0.f;

    gemm_tf32_main(g_AO, W, m0, n0, acc);

    const int tid  = threadIdx.x;
    const int lane = tid & 31, warp = tid >> 5;
    const int wm = warp >> 2, wn = warp & 3;
    const int g  = lane >> 2, tg = lane & 3;

#pragma unroll
    for (int fn = 0; fn < 4; fn++) {
        const int n = n0 + wn * 32 + fn * 8 + 2 * tg;
        const float b0 = Bb[n], b1 = Bb[n + 1];
#pragma unroll
        for (int fm = 0; fm < 4; fm++) {
#pragma unroll
            for (int half = 0; half < 2; half++) {
                const int m = m0 + wm * 64 + fm * 16 + g + half * 8;
                *(float2*)(Out + (size_t)m * DMODEL + n) =
                    make_float2(acc[fm][fn][half * 2 + 0] + b0,
                                acc[fm][fn][half * 2 + 1] + b1);
            }
        }
    }
}

// ============ Flash attention: fp16 split-precision (hi/lo) HMMA ===============
// Br=128, Bc=64, 8 warps, warp tile 16x64 (fm=1, fn=8): each warp owns FULL rows
// so online-softmax statistics span all 64 tile columns within one warp.
#define APITCH 36
#define OFF_QHI 0
#define OFF_QLO (OFF_QHI + 128 * APITCH)
#define OFF_KHI (OFF_QLO + 128 * APITCH)
#define OFF_KLO (OFF_KHI + 64 * APITCH)
#define OFF_VHI (OFF_KLO + 64 * APITCH)
#define OFF_VLO (OFF_VHI + 64 * APITCH)
#define OFF_PHI (OFF_VLO + 64 * APITCH)
#define OFF_PLO (OFF_PHI + 128 * APITCH)
#define ATTN_SMEM_U32 (OFF_PLO + 128 * APITCH)
#define ATTN_SMEM_BYTES (ATTN_SMEM_U32 * 4)      // 110592

__device__ __forceinline__ uint32_t h2u(half2 h) {
    return *reinterpret_cast<uint32_t*>(&h);
}

__device__ __forceinline__ void split_pack(float x, float y, uint32_t& hi, uint32_t& lo) {
    half2 h = __floats2half2_rn(x, y);
    float lx = x - __low2float(h);
    float ly = y - __high2float(h);
    half2 l = __floats2half2_rn(lx, ly);
    hi = h2u(h);
    lo = h2u(l);
}

__device__ __forceinline__ void mma_f16(float c[4], const uint32_t a[4],
                                        uint32_t b0, uint32_t b1) {
    asm volatile(
        "mma.sync.aligned.m16n8k16.row.col.f32.f16.f16.f32 "
        "{%0,%1,%2,%3}, {%4,%5,%6,%7}, {%8,%9}, {%0,%1,%2,%3};"
        : "+f"(c[0]), "+f"(c[1]), "+f"(c[2]), "+f"(c[3])
        : "r"(a[0]), "r"(a[1]), "r"(a[2]), "r"(a[3]), "r"(b0), "r"(b1));
}

__global__ __launch_bounds__(256, 2) void attn_hmma_kernel() {
    extern __shared__ uint32_t smu[];
    uint32_t* Qhi = smu + OFF_QHI;
    uint32_t* Qlo = smu + OFF_QLO;
    uint32_t* Khi = smu + OFF_KHI;
    uint32_t* Klo = smu + OFF_KLO;
    uint32_t* Vhi = smu + OFF_VHI;
    uint32_t* Vlo = smu + OFF_VLO;
    uint32_t* Phi = smu + OFF_PHI;
    uint32_t* Plo = smu + OFF_PLO;

    const int qb = 15 - blockIdx.x;            // long CTAs first
    const int bh = blockIdx.y;
    const size_t base = (size_t)bh * SLEN * DKH;
    const float* Qh = g_Q + base;
    const float* Kh = g_K + base;
    const float* Vh = g_V + base;

    const int tid  = threadIdx.x;
    const int lane = tid & 31, warp = tid >> 5;
    const int g  = lane >> 2, tg = lane & 3;
    const int row0 = warp * 16;                // warp owns rows row0..row0+15 (local)

    // ---- load Q tile (scaled by 1/sqrt(dk)=0.125), split-pack ----
#pragma unroll
    for (int j = 0; j < 8; j++) {
        int t   = tid + j * 256;       // 0..2047
        int row = t >> 4;              // 0..127
        int dq  = (t & 15) << 2;       // 0..60
        float4 v = *(const float4*)(Qh + (size_t)(qb * 128 + row) * DKH + dq);
        uint32_t h0, l0, h1, l1;
        split_pack(v.x * 0.125f, v.y * 0.125f, h0, l0);
        split_pack(v.z * 0.125f, v.w * 0.125f, h1, l1);
        int o = row * APITCH + (dq >> 1);
        Qhi[o] = h0; Qhi[o + 1] = h1;
        Qlo[o] = l0; Qlo[o + 1] = l1;
    }

    float acc_o[8][4];
#pragma unroll
    for (int j = 0; j < 8; j++)
#pragma unroll
        for (int t = 0; t < 4; t++) acc_o[j][t] = 0.f;
    float m_run[2] = {-1.0e30f, -1.0e30f};
    float l_run[2] = {0.f, 0.f};

    const int ntiles = 2 * (qb + 1);
    for (int kb = 0; kb < ntiles; kb++) {
        __syncthreads();   // (a) prior PV reads of K/V done

        // ---- load K tile, split-pack ----
#pragma unroll
        for (int j = 0; j < 4; j++) {
            int t   = tid + j * 256;   // 0..1023
            int row = t >> 4;          // 0..63
            int dq  = (t & 15) << 2;
            float4 v = *(const float4*)(Kh + (size_t)(kb * 64 + row) * DKH + dq);
            uint32_t h0, l0, h1, l1;
            split_pack(v.x, v.y, h0, l0);
            split_pack(v.z, v.w, h1, l1);
            int o = row * APITCH + (dq >> 1);
            Khi[o] = h0; Khi[o + 1] = h1;
            Klo[o] = l0; Klo[o + 1] = l1;
        }
        // ---- load V tile transposed-packed: Vhi[d][key-pair] ----
#pragma unroll
        for (int j = 0; j < 2; j++) {
            int t  = tid + j * 256;    // 0..511
            int r  = t >> 4;           // key-pair 0..31
            int dq = (t & 15) << 2;
            float4 va = *(const float4*)(Vh + (size_t)(kb * 64 + 2 * r) * DKH + dq);
            float4 vb = *(const float4*)(Vh + (size_t)(kb * 64 + 2 * r + 1) * DKH + dq);
            float a_[4] = {va.x, va.y, va.z, va.w};
            float b_[4] = {vb.x, vb.y, vb.z, vb.w};
#pragma unroll
            for (int i = 0; i < 4; i++) {
                uint32_t h, l;
                split_pack(a_[i], b_[i], h, l);
                Vhi[(dq + i) * APITCH + r] = h;
                Vlo[(dq + i) * APITCH + r] = l;
            }
        }
        __syncthreads();   // (b) K/V (and Q on iter 0) visible

        const bool active = (kb * 64 <= qb * 128 + row0 + 15);

        if (active) {
            // ---- S = Q K^T (3-term split), 16 rows x 64 cols ----
            float s_acc[8][4];
#pragma unroll
            for (int j = 0; j < 8; j++)
#pragma unroll
                for (int t = 0; t < 4; t++) s_acc[j][t] = 0.f;

#pragma unroll
            for (int ks = 0; ks < 4; ks++) {
                uint32_t ahi[4], alo[4];
                {
                    int r0 = (row0 + g) * APITCH + ks * 8 + tg;
                    ahi[0] = Qhi[r0];
                    ahi[1] = Qhi[r0 + 8 * APITCH];
                    ahi[2] = Qhi[r0 + 4];
                    ahi[3] = Qhi[r0 + 8 * APITCH + 4];
                    alo[0] = Qlo[r0];
                    alo[1] = Qlo[r0 + 8 * APITCH];
                    alo[2] = Qlo[r0 + 4];
                    alo[3] = Qlo[r0 + 8 * APITCH + 4];
                }
#pragma unroll
                for (int fn = 0; fn < 8; fn++) {
                    int n0 = (fn * 8 + g) * APITCH + ks * 8 + tg;
                    uint32_t bh0 = Khi[n0], bh1 = Khi[n0 + 4];
                    uint32_t bl0 = Klo[n0], bl1 = Klo[n0 + 4];
                    mma_f16(s_acc[fn], ahi, bh0, bh1);
                    mma_f16(s_acc[fn], ahi, bl0, bl1);
                    mma_f16(s_acc[fn], alo, bh0, bh1);
                }
            }

            // ---- mask + online softmax + pack P ----
            const bool diag = (kb >= 2 * qb);
#pragma unroll
            for (int h = 0; h < 2; h++) {
                if (diag) {
                    int row = qb * 128 + row0 + g + 8 * h;
#pragma unroll
                    for (int fn = 0; fn < 8; fn++) {
                        int col = kb * 64 + fn * 8 + 2 * tg;
                        if (col > row)     s_acc[fn][h * 2 + 0] = -1.0e30f;
                        if (col + 1 > row) s_acc[fn][h * 2 + 1] = -1.0e30f;
                    }
                }
                float mx = s_acc[0][h * 2];
#pragma unroll
                for (int fn = 0; fn < 8; fn++) {
                    mx = fmaxf(mx, s_acc[fn][h * 2 + 0]);
                    mx = fmaxf(mx, s_acc[fn][h * 2 + 1]);
                }
                mx = fmaxf(mx, __shfl_xor_sync(0xffffffffu, mx, 1));
                mx = fmaxf(mx, __shfl_xor_sync(0xffffffffu, mx, 2));
                float mn   = fmaxf(m_run[h], mx);
                float corr = __expf(m_run[h] - mn);
                float rs = 0.f;
                float p[16];
#pragma unroll
                for (int fn = 0; fn < 8; fn++) {
                    p[fn * 2 + 0] = __expf(s_acc[fn][h * 2 + 0] - mn);
                    p[fn * 2 + 1] = __expf(s_acc[fn][h * 2 + 1] - mn);
                    rs += p[fn * 2 + 0] + p[fn * 2 + 1];
                }
                rs += __shfl_xor_sync(0xffffffffu, rs, 1);
                rs += __shfl_xor_sync(0xffffffffu, rs, 2);
                l_run[h] = l_run[h] * corr + rs;
                m_run[h] = mn;
#pragma unroll
                for (int fn = 0; fn < 8; fn++) {
                    acc_o[fn][h * 2 + 0] *= corr;
                    acc_o[fn][h * 2 + 1] *= corr;
                }
                int row_l = row0 + g + 8 * h;
#pragma unroll
                for (int fn = 0; fn < 8; fn++) {
                    uint32_t hi, lo;
                    split_pack(p[fn * 2 + 0], p[fn * 2 + 1], hi, lo);
                    int kc = row_l * APITCH + fn * 4 + tg;
                    Phi[kc] = hi;
                    Plo[kc] = lo;
                }
            }

            // ---- O += P V (3-term split) ----
            __syncwarp();   // P rows are warp-private; warp-level visibility only
#pragma unroll
            for (int ks = 0; ks < 4; ks++) {
                uint32_t ahi[4], alo[4];
                {
                    int r0 = (row0 + g) * APITCH + ks * 8 + tg;
                    ahi[0] = Phi[r0];
                    ahi[1] = Phi[r0 + 8 * APITCH];
                    ahi[2] = Phi[r0 + 4];
                    ahi[3] = Phi[r0 + 8 * APITCH + 4];
                    alo[0] = Plo[r0];
                    alo[1] = Plo[r0 + 8 * APITCH];
                    alo[2] = Plo[r0 + 4];
                    alo[3] = Plo[r0 + 8 * APITCH + 4];
                }
#pragma unroll
                for (int fn = 0; fn < 8; fn++) {
                    int n0 = (fn * 8 + g) * APITCH + ks * 8 + tg;
                    uint32_t bh0 = Vhi[n0], bh1 = Vhi[n0 + 4];
                    uint32_t bl0 = Vlo[n0], bl1 = Vlo[n0 + 4];
                    mma_f16(acc_o[fn], ahi, bh0, bh1);
                    mma_f16(acc_o[fn], ahi, bl0, bl1);
                    mma_f16(acc_o[fn], alo, bh0, bh1);
                }
            }
        }
    }

    // ---- normalize + write O ----
    const int bb = bh >> 4, hh = bh & 15;
#pragma unroll
    for (int h = 0; h < 2; h++) {
        float invl = 1.0f / l_run[h];
        int row = qb * 128 + row0 + g + 8 * h;
        float* dst = g_AO + ((size_t)bb * SLEN + row) * DMODEL + hh * DKH;
#pragma unroll
        for (int fn = 0; fn < 8; fn++) {
            int dd = fn * 8 + 2 * tg;
            *(float2*)(dst + dd) =
                make_float2(acc_o[fn][h * 2 + 0] * invl,
                            acc_o[fn][h * 2 + 1] * invl);
        }
    }
}

// ---------------- launch -------------------------------------------------------
extern "C" void kernel_launch(void* const* d_in, const int* in_sizes, int n_in,
                              void* d_out, int out_size) {
    const float* q  = (const float*)d_in[0];
    const float* k  = (const float*)d_in[1];
    const float* v  = (const float*)d_in[2];
    // d_in[3] = mask (int32 tril) — causal, applied analytically
    const float* wq = (const float*)d_in[4];
    const float* bq = (const float*)d_in[5];
    const float* wk = (const float*)d_in[6];
    const float* bk = (const float*)d_in[7];
    const float* wv = (const float*)d_in[8];
    const float* bv = (const float*)d_in[9];
    const float* wo = (const float*)d_in[10];
    const float* bo = (const float*)d_in[11];
    float* out = (float*)d_out;

    cudaFuncSetAttribute(qkv_tf32_kernel, cudaFuncAttributeMaxDynamicSharedMemorySize, GEMM_SMEM);
    cudaFuncSetAttribute(outproj_tf32_kernel, cudaFuncAttributeMaxDynamicSharedMemorySize, GEMM_SMEM);
    cudaFuncSetAttribute(attn_hmma_kernel, cudaFuncAttributeMaxDynamicSharedMemorySize, ATTN_SMEM_BYTES);

    qkv_tf32_kernel<<<dim3(DMODEL / BN, MTOT / BM, 3), 256, GEMM_SMEM>>>(
        q, k, v, wq, wk, wv, bq, bk, bv);

    attn_hmma_kernel<<<dim3(SLEN / 128, NB * NHEAD), 256, ATTN_SMEM_BYTES>>>();

    outproj_tf32_kernel<<<dim3(DMODEL / BN, MTOT / BM), 256, GEMM_SMEM>>>(wo, bo, out);
}

// round 7
// speedup vs baseline: 6.7780x; 1.0977x over previous
#include <cuda_runtime.h>
#include <cuda_fp16.h>
#include <cstdint>

#define SLEN    2048
#define DMODEL  1024
#define NHEAD   16
#define DKH     64
#define NB      4
#define MTOT    (NB * SLEN)     // 8192

// ---------------- scratch (allocation-free: __device__ globals) ----------------
__device__ float g_Q[(size_t)NB * NHEAD * SLEN * DKH];   // [B,H,S,64]
__device__ float g_K[(size_t)NB * NHEAD * SLEN * DKH];
__device__ float g_V[(size_t)NB * NHEAD * SLEN * DKH];
__device__ float g_AO[(size_t)MTOT * DMODEL];            // [B*S, H*64]

// pre-converted tf32 operands, pair-permuted within each 8-k group:
// u32 order per group = [k0,k4,k1,k5,k2,k6,k3,k7]
__device__ uint32_t g_Xt[(size_t)3 * MTOT * DMODEL];     // q,k,v inputs
__device__ uint32_t g_Wt[(size_t)4 * DMODEL * DMODEL];   // wq,wk,wv,wo
__device__ uint32_t g_AOt[(size_t)MTOT * DMODEL];

// ---------------- helpers ------------------------------------------------------
__device__ __forceinline__ uint32_t f2tf32(float f) {
    uint32_t u;
    asm("cvt.rna.tf32.f32 %0, %1;" : "=r"(u) : "f"(f));
    return u;
}

__device__ __forceinline__ void mma_tf32(float c[4], const uint32_t a[4], const uint32_t b[2]) {
    asm volatile(
        "mma.sync.aligned.m16n8k8.row.col.f32.tf32.tf32.f32 "
        "{%0,%1,%2,%3}, {%4,%5,%6,%7}, {%8,%9}, {%0,%1,%2,%3};"
        : "+f"(c[0]), "+f"(c[1]), "+f"(c[2]), "+f"(c[3])
        : "r"(a[0]), "r"(a[1]), "r"(a[2]), "r"(a[3]), "r"(b[0]), "r"(b[1]));
}

__device__ __forceinline__ uint32_t smem_u32(const void* p) {
    uint32_t a;
    asm("{ .reg .u64 t; cvta.to.shared.u64 t, %1; cvt.u32.u64 %0, t; }" : "=r"(a) : "l"(p));
    return a;
}

__device__ __forceinline__ void cp16(uint32_t dst, const void* src) {
    asm volatile("cp.async.cg.shared.global [%0], [%1], 16;" :: "r"(dst), "l"(src));
}
#define CP_COMMIT() asm volatile("cp.async.commit_group;")
#define CP_WAIT(n)  asm volatile("cp.async.wait_group %0;" :: "n"(n))

// ---------------- tf32 pre-convert with pair permutation -----------------------
// sel: 0..2 = q/k/v -> g_Xt, 3..6 = wq/wk/wv/wo -> g_Wt, 7 = g_AO -> g_AOt
__global__ __launch_bounds__(256) void conv_tf32_kernel(const float* __restrict__ src,
                                                        int sel, int n8)
{
    int i = blockIdx.x * 256 + threadIdx.x;
    if (i >= n8) return;
    const float4* s = (const float4*)src;
    uint4* d;
    if (sel < 3) {
        d = (uint4*)(g_Xt + (size_t)sel * MTOT * DMODEL);
    } else if (sel < 7) {
        d = (uint4*)(g_Wt + (size_t)(sel - 3) * DMODEL * DMODEL);
    } else {
        s = (const float4*)g_AO;
        d = (uint4*)g_AOt;
    }
    float4 v0 = s[2 * i];
    float4 v1 = s[2 * i + 1];
    uint4 o0, o1;
    o0.x = f2tf32(v0.x); o0.y = f2tf32(v1.x);   // k0,k4
    o0.z = f2tf32(v0.y); o0.w = f2tf32(v1.y);   // k1,k5
    o1.x = f2tf32(v0.z); o1.y = f2tf32(v1.z);   // k2,k6
    o1.z = f2tf32(v0.w); o1.w = f2tf32(v1.w);   // k3,k7
    d[2 * i]     = o0;
    d[2 * i + 1] = o1;
}

// ======================= tf32 tensor-core GEMM =================================
// C[128,128] = X[M,1024] @ W[N,1024]^T, operands pre-tf32 pair-permuted.
// BK=32, smem pitch 40 u32 (LDS.64 fragment loads conflict-free), 2-stage cp.async.
#define BK2 32
#define P40 40
#define STAGEU (128 * P40)                    // u32 per operand per stage
#define GEMM_SMEM (2 * 2 * STAGEU * 4)        // 81920 bytes

__device__ __forceinline__ void gemm_tf32_main(const uint32_t* __restrict__ X,
                                               const uint32_t* __restrict__ W,
                                               int m0, int n0,
                                               float acc[4][4][4]) {
    extern __shared__ uint32_t su[];
    const int tid  = threadIdx.x;
    const int lane = tid & 31, warp = tid >> 5;
    const int wm = warp >> 2, wn = warp & 3;
    const int g  = lane >> 2, tg = lane & 3;

    const uint32_t sb = smem_u32(su);
    const int lrow = tid >> 3;                // 0..127 (two passes of 256 -> use seg)
    (void)lrow;

#define ISSUE_TILE(kt, s)                                                           \
    do {                                                                            \
        uint32_t _b = sb + ((uint32_t)(s) * 2 * STAGEU) * 4u;                       \
        _Pragma("unroll")                                                           \
        for (int _j = 0; _j < 4; _j++) {                                            \
            int _seg = tid + _j * 256;        /* 0..1023 */                         \
            int _row = _seg >> 3;             /* 0..127 */                          \
            int _ch  = _seg & 7;              /* 16B chunk 0..7 */                  \
            uint32_t _off = (uint32_t)(_row * P40 * 4 + _ch * 16);                  \
            cp16(_b + _off,                                                         \
                 (const char*)(X + (size_t)(m0 + _row) * DMODEL + (kt) * BK2) + _ch * 16); \
            cp16(_b + (uint32_t)(STAGEU * 4) + _off,                                \
                 (const char*)(W + (size_t)(n0 + _row) * DMODEL + (kt) * BK2) + _ch * 16); \
        }                                                                           \
    } while (0)

    const int NT = DMODEL / BK2;              // 32
    ISSUE_TILE(0, 0); CP_COMMIT();
    ISSUE_TILE(1, 1); CP_COMMIT();

    for (int kt = 0; kt < NT; kt++) {
        CP_WAIT(1);
        __syncthreads();

        const int s = kt & 1;
        const uint32_t* Asb = su + s * 2 * STAGEU;
        const uint32_t* Bsb = Asb + STAGEU;

#pragma unroll
        for (int kg = 0; kg < 4; kg++) {      // four k8 groups in BK2=32
            const int colb = kg * 8 + 2 * tg;
            uint32_t a[4][4], b[4][2];
#pragma unroll
            for (int fm = 0; fm < 4; fm++) {
                const int r = wm * 64 + fm * 16 + g;
                uint2 t0 = *(const uint2*)(Asb + r * P40 + colb);
                uint2 t1 = *(const uint2*)(Asb + (r + 8) * P40 + colb);
                a[fm][0] = t0.x; a[fm][2] = t0.y;
                a[fm][1] = t1.x; a[fm][3] = t1.y;
            }
#pragma unroll
            for (int fn = 0; fn < 4; fn++) {
                const int r = wn * 32 + fn * 8 + g;
                uint2 t = *(const uint2*)(Bsb + r * P40 + colb);
                b[fn][0] = t.x; b[fn][1] = t.y;
            }
#pragma unroll
            for (int fm = 0; fm < 4; fm++)
#pragma unroll
                for (int fn = 0; fn < 4; fn++)
                    mma_tf32(acc[fm][fn], a[fm], b[fn]);
        }

        __syncthreads();
        if (kt + 2 < NT) ISSUE_TILE(kt + 2, s);
        CP_COMMIT();
    }
#undef ISSUE_TILE
}

// ---------------- QKV projection, head-split output ---------------------------
__global__ __launch_bounds__(256, 2) void qkv_tf32_kernel(
    const float* __restrict__ bq, const float* __restrict__ bk, const float* __restrict__ bv)
{
    const int z = blockIdx.z;
    const uint32_t* X = g_Xt + (size_t)z * MTOT * DMODEL;
    const uint32_t* W = g_Wt + (size_t)z * DMODEL * DMODEL;
    const float* Bb   = (z == 0) ? bq : (z == 1) ? bk : bv;
    float* Out        = (z == 0) ? g_Q : (z == 1) ? g_K : g_V;

    const int m0 = blockIdx.y * 128, n0 = blockIdx.x * 128;
    float acc[4][4][4];
#pragma unroll
    for (int i = 0; i < 4; i++)
#pragma unroll
        for (int j = 0; j < 4; j++)
#pragma unroll
            for (int t = 0; t < 4; t++) acc[i][j][t] = 0.f;

    gemm_tf32_main(X, W, m0, n0, acc);

    const int tid  = threadIdx.x;
    const int lane = tid & 31, warp = tid >> 5;
    const int wm = warp >> 2, wn = warp & 3;
    const int g  = lane >> 2, tg = lane & 3;

#pragma unroll
    for (int fn = 0; fn < 4; fn++) {
        const int n  = n0 + wn * 32 + fn * 8 + 2 * tg;
        const int hh = n >> 6, dd = n & 63;
        const float b0 = Bb[n], b1 = Bb[n + 1];
#pragma unroll
        for (int fm = 0; fm < 4; fm++) {
#pragma unroll
            for (int half = 0; half < 2; half++) {
                const int m  = m0 + wm * 64 + fm * 16 + g + half * 8;
                const int bb = m >> 11;
                const int ss = m & (SLEN - 1);
                float* dst = Out + (((size_t)bb * NHEAD + hh) * SLEN + ss) * DKH + dd;
                *(float2*)dst = make_float2(acc[fm][fn][half * 2 + 0] + b0,
                                            acc[fm][fn][half * 2 + 1] + b1);
            }
        }
    }
}

// ---------------- output projection -------------------------------------------
__global__ __launch_bounds__(256, 2) void outproj_tf32_kernel(
    const float* __restrict__ Bb, float* __restrict__ Out)
{
    const uint32_t* W = g_Wt + (size_t)3 * DMODEL * DMODEL;
    const int m0 = blockIdx.y * 128, n0 = blockIdx.x * 128;
    float acc[4][4][4];
#pragma unroll
    for (int i = 0; i < 4; i++)
#pragma unroll
        for (int j = 0; j < 4; j++)
#pragma unroll
            for (int t = 0; t < 4; t++) acc[i][j][t] = 0.f;

    gemm_tf32_main(g_AOt, W, m0, n0, acc);

    const int tid  = threadIdx.x;
    const int lane = tid & 31, warp = tid >> 5;
    const int wm = warp >> 2, wn = warp & 3;
    const int g  = lane >> 2, tg = lane & 3;

#pragma unroll
    for (int fn = 0; fn < 4; fn++) {
        const int n = n0 + wn * 32 + fn * 8 + 2 * tg;
        const float b0 = Bb[n], b1 = Bb[n + 1];
#pragma unroll
        for (int fm = 0; fm < 4; fm++) {
#pragma unroll
            for (int half = 0; half < 2; half++) {
                const int m = m0 + wm * 64 + fm * 16 + g + half * 8;
                *(float2*)(Out + (size_t)m * DMODEL + n) =
                    make_float2(acc[fm][fn][half * 2 + 0] + b0,
                                acc[fm][fn][half * 2 + 1] + b1);
            }
        }
    }
}

// ============ Flash attention: fp16 split-precision HMMA (unchanged R5) ========
#define APITCH 36
#define OFF_QHI 0
#define OFF_QLO (OFF_QHI + 128 * APITCH)
#define OFF_KHI (OFF_QLO + 128 * APITCH)
#define OFF_KLO (OFF_KHI + 64 * APITCH)
#define OFF_VHI (OFF_KLO + 64 * APITCH)
#define OFF_VLO (OFF_VHI + 64 * APITCH)
#define OFF_PHI (OFF_VLO + 64 * APITCH)
#define OFF_PLO (OFF_PHI + 128 * APITCH)
#define ATTN_SMEM_U32 (OFF_PLO + 128 * APITCH)
#define ATTN_SMEM_BYTES (ATTN_SMEM_U32 * 4)      // 110592

__device__ __forceinline__ uint32_t h2u(half2 h) {
    return *reinterpret_cast<uint32_t*>(&h);
}

__device__ __forceinline__ void split_pack(float x, float y, uint32_t& hi, uint32_t& lo) {
    half2 h = __floats2half2_rn(x, y);
    float lx = x - __low2float(h);
    float ly = y - __high2float(h);
    half2 l = __floats2half2_rn(lx, ly);
    hi = h2u(h);
    lo = h2u(l);
}

__device__ __forceinline__ void mma_f16(float c[4], const uint32_t a[4],
                                        uint32_t b0, uint32_t b1) {
    asm volatile(
        "mma.sync.aligned.m16n8k16.row.col.f32.f16.f16.f32 "
        "{%0,%1,%2,%3}, {%4,%5,%6,%7}, {%8,%9}, {%0,%1,%2,%3};"
        : "+f"(c[0]), "+f"(c[1]), "+f"(c[2]), "+f"(c[3])
        : "r"(a[0]), "r"(a[1]), "r"(a[2]), "r"(a[3]), "r"(b0), "r"(b1));
}

__global__ __launch_bounds__(256, 2) void attn_hmma_kernel() {
    extern __shared__ uint32_t smu[];
    uint32_t* Qhi = smu + OFF_QHI;
    uint32_t* Qlo = smu + OFF_QLO;
    uint32_t* Khi = smu + OFF_KHI;
    uint32_t* Klo = smu + OFF_KLO;
    uint32_t* Vhi = smu + OFF_VHI;
    uint32_t* Vlo = smu + OFF_VLO;
    uint32_t* Phi = smu + OFF_PHI;
    uint32_t* Plo = smu + OFF_PLO;

    const int qb = 15 - blockIdx.x;            // long CTAs first
    const int bh = blockIdx.y;
    const size_t base = (size_t)bh * SLEN * DKH;
    const float* Qh = g_Q + base;
    const float* Kh = g_K + base;
    const float* Vh = g_V + base;

    const int tid  = threadIdx.x;
    const int lane = tid & 31, warp = tid >> 5;
    const int g  = lane >> 2, tg = lane & 3;
    const int row0 = warp * 16;

#pragma unroll
    for (int j = 0; j < 8; j++) {
        int t   = tid + j * 256;
        int row = t >> 4;
        int dq  = (t & 15) << 2;
        float4 v = *(const float4*)(Qh + (size_t)(qb * 128 + row) * DKH + dq);
        uint32_t h0, l0, h1, l1;
        split_pack(v.x * 0.125f, v.y * 0.125f, h0, l0);
        split_pack(v.z * 0.125f, v.w * 0.125f, h1, l1);
        int o = row * APITCH + (dq >> 1);
        Qhi[o] = h0; Qhi[o + 1] = h1;
        Qlo[o] = l0; Qlo[o + 1] = l1;
    }

    float acc_o[8][4];
#pragma unroll
    for (int j = 0; j < 8; j++)
#pragma unroll
        for (int t = 0; t < 4; t++) acc_o[j][t] = 0.f;
    float m_run[2] = {-1.0e30f, -1.0e30f};
    float l_run[2] = {0.f, 0.f};

    const int ntiles = 2 * (qb + 1);
    for (int kb = 0; kb < ntiles; kb++) {
        __syncthreads();

#pragma unroll
        for (int j = 0; j < 4; j++) {
            int t   = tid + j * 256;
            int row = t >> 4;
            int dq  = (t & 15) << 2;
            float4 v = *(const float4*)(Kh + (size_t)(kb * 64 + row) * DKH + dq);
            uint32_t h0, l0, h1, l1;
            split_pack(v.x, v.y, h0, l0);
            split_pack(v.z, v.w, h1, l1);
            int o = row * APITCH + (dq >> 1);
            Khi[o] = h0; Khi[o + 1] = h1;
            Klo[o] = l0; Klo[o + 1] = l1;
        }
#pragma unroll
        for (int j = 0; j < 2; j++) {
            int t  = tid + j * 256;
            int r  = t >> 4;
            int dq = (t & 15) << 2;
            float4 va = *(const float4*)(Vh + (size_t)(kb * 64 + 2 * r) * DKH + dq);
            float4 vb = *(const float4*)(Vh + (size_t)(kb * 64 + 2 * r + 1) * DKH + dq);
            float a_[4] = {va.x, va.y, va.z, va.w};
            float b_[4] = {vb.x, vb.y, vb.z, vb.w};
#pragma unroll
            for (int i = 0; i < 4; i++) {
                uint32_t h, l;
                split_pack(a_[i], b_[i], h, l);
                Vhi[(dq + i) * APITCH + r] = h;
                Vlo[(dq + i) * APITCH + r] = l;
            }
        }
        __syncthreads();

        const bool active = (kb * 64 <= qb * 128 + row0 + 15);

        if (active) {
            float s_acc[8][4];
#pragma unroll
            for (int j = 0; j < 8; j++)
#pragma unroll
                for (int t = 0; t < 4; t++) s_acc[j][t] = 0.f;

#pragma unroll
            for (int ks = 0; ks < 4; ks++) {
                uint32_t ahi[4], alo[4];
                {
                    int r0 = (row0 + g) * APITCH + ks * 8 + tg;
                    ahi[0] = Qhi[r0];
                    ahi[1] = Qhi[r0 + 8 * APITCH];
                    ahi[2] = Qhi[r0 + 4];
                    ahi[3] = Qhi[r0 + 8 * APITCH + 4];
                    alo[0] = Qlo[r0];
                    alo[1] = Qlo[r0 + 8 * APITCH];
                    alo[2] = Qlo[r0 + 4];
                    alo[3] = Qlo[r0 + 8 * APITCH + 4];
                }
#pragma unroll
                for (int fn = 0; fn < 8; fn++) {
                    int n0 = (fn * 8 + g) * APITCH + ks * 8 + tg;
                    uint32_t bh0 = Khi[n0], bh1 = Khi[n0 + 4];
                    uint32_t bl0 = Klo[n0], bl1 = Klo[n0 + 4];
                    mma_f16(s_acc[fn], ahi, bh0, bh1);
                    mma_f16(s_acc[fn], ahi, bl0, bl1);
                    mma_f16(s_acc[fn], alo, bh0, bh1);
                }
            }

            const bool diag = (kb >= 2 * qb);
#pragma unroll
            for (int h = 0; h < 2; h++) {
                if (diag) {
                    int row = qb * 128 + row0 + g + 8 * h;
#pragma unroll
                    for (int fn = 0; fn < 8; fn++) {
                        int col = kb * 64 + fn * 8 + 2 * tg;
                        if (col > row)     s_acc[fn][h * 2 + 0] = -1.0e30f;
                        if (col + 1 > row) s_acc[fn][h * 2 + 1] = -1.0e30f;
                    }
                }
                float mx = s_acc[0][h * 2];
#pragma unroll
                for (int fn = 0; fn < 8; fn++) {
                    mx = fmaxf(mx, s_acc[fn][h * 2 + 0]);
                    mx = fmaxf(mx, s_acc[fn][h * 2 + 1]);
                }
                mx = fmaxf(mx, __shfl_xor_sync(0xffffffffu, mx, 1));
                mx = fmaxf(mx, __shfl_xor_sync(0xffffffffu, mx, 2));
                float mn   = fmaxf(m_run[h], mx);
                float corr = __expf(m_run[h] - mn);
                float rs = 0.f;
                float p[16];
#pragma unroll
                for (int fn = 0; fn < 8; fn++) {
                    p[fn * 2 + 0] = __expf(s_acc[fn][h * 2 + 0] - mn);
                    p[fn * 2 + 1] = __expf(s_acc[fn][h * 2 + 1] - mn);
                    rs += p[fn * 2 + 0] + p[fn * 2 + 1];
                }
                rs += __shfl_xor_sync(0xffffffffu, rs, 1);
                rs += __shfl_xor_sync(0xffffffffu, rs, 2);
                l_run[h] = l_run[h] * corr + rs;
                m_run[h] = mn;
#pragma unroll
                for (int fn = 0; fn < 8; fn++) {
                    acc_o[fn][h * 2 + 0] *= corr;
                    acc_o[fn][h * 2 + 1] *= corr;
                }
                int row_l = row0 + g + 8 * h;
#pragma unroll
                for (int fn = 0; fn < 8; fn++) {
                    uint32_t hi, lo;
                    split_pack(p[fn * 2 + 0], p[fn * 2 + 1], hi, lo);
                    int kc = row_l * APITCH + fn * 4 + tg;
                    Phi[kc] = hi;
                    Plo[kc] = lo;
                }
            }

            __syncwarp();
#pragma unroll
            for (int ks = 0; ks < 4; ks++) {
                uint32_t ahi[4], alo[4];
                {
                    int r0 = (row0 + g) * APITCH + ks * 8 + tg;
                    ahi[0] = Phi[r0];
                    ahi[1] = Phi[r0 + 8 * APITCH];
                    ahi[2] = Phi[r0 + 4];
                    ahi[3] = Phi[r0 + 8 * APITCH + 4];
                    alo[0] = Plo[r0];
                    alo[1] = Plo[r0 + 8 * APITCH];
                    alo[2] = Plo[r0 + 4];
                    alo[3] = Plo[r0 + 8 * APITCH + 4];
                }
#pragma unroll
                for (int fn = 0; fn < 8; fn++) {
                    int n0 = (fn * 8 + g) * APITCH + ks * 8 + tg;
                    uint32_t bh0 = Vhi[n0], bh1 = Vhi[n0 + 4];
                    uint32_t bl0 = Vlo[n0], bl1 = Vlo[n0 + 4];
                    mma_f16(acc_o[fn], ahi, bh0, bh1);
                    mma_f16(acc_o[fn], ahi, bl0, bl1);
                    mma_f16(acc_o[fn], alo, bh0, bh1);
                }
            }
        }
    }

    const int bb = bh >> 4, hh = bh & 15;
#pragma unroll
    for (int h = 0; h < 2; h++) {
        float invl = 1.0f / l_run[h];
        int row = qb * 128 + row0 + g + 8 * h;
        float* dst = g_AO + ((size_t)bb * SLEN + row) * DMODEL + hh * DKH;
#pragma unroll
        for (int fn = 0; fn < 8; fn++) {
            int dd = fn * 8 + 2 * tg;
            *(float2*)(dst + dd) =
                make_float2(acc_o[fn][h * 2 + 0] * invl,
                            acc_o[fn][h * 2 + 1] * invl);
        }
    }
}

// ---------------- launch -------------------------------------------------------
extern "C" void kernel_launch(void* const* d_in, const int* in_sizes, int n_in,
                              void* d_out, int out_size) {
    const float* q  = (const float*)d_in[0];
    const float* k  = (const float*)d_in[1];
    const float* v  = (const float*)d_in[2];
    // d_in[3] = mask (int32 tril) — causal, applied analytically
    const float* wq = (const float*)d_in[4];
    const float* bq = (const float*)d_in[5];
    const float* wk = (const float*)d_in[6];
    const float* bk = (const float*)d_in[7];
    const float* wv = (const float*)d_in[8];
    const float* bv = (const float*)d_in[9];
    const float* wo = (const float*)d_in[10];
    const float* bo = (const float*)d_in[11];
    float* out = (float*)d_out;

    cudaFuncSetAttribute(qkv_tf32_kernel, cudaFuncAttributeMaxDynamicSharedMemorySize, GEMM_SMEM);
    cudaFuncSetAttribute(outproj_tf32_kernel, cudaFuncAttributeMaxDynamicSharedMemorySize, GEMM_SMEM);
    cudaFuncSetAttribute(attn_hmma_kernel, cudaFuncAttributeMaxDynamicSharedMemorySize, ATTN_SMEM_BYTES);

    const int n8x = MTOT * DMODEL / 8;       // 1048576
    const int n8w = DMODEL * DMODEL / 8;     // 131072
    conv_tf32_kernel<<<n8x / 256, 256>>>(q,  0, n8x);
    conv_tf32_kernel<<<n8x / 256, 256>>>(k,  1, n8x);
    conv_tf32_kernel<<<n8x / 256, 256>>>(v,  2, n8x);
    conv_tf32_kernel<<<n8w / 256, 256>>>(wq, 3, n8w);
    conv_tf32_kernel<<<n8w / 256, 256>>>(wk, 4, n8w);
    conv_tf32_kernel<<<n8w / 256, 256>>>(wv, 5, n8w);
    conv_tf32_kernel<<<n8w / 256, 256>>>(wo, 6, n8w);

    qkv_tf32_kernel<<<dim3(DMODEL / 128, MTOT / 128, 3), 256, GEMM_SMEM>>>(bq, bk, bv);

    attn_hmma_kernel<<<dim3(SLEN / 128, NB * NHEAD), 256, ATTN_SMEM_BYTES>>>();

    conv_tf32_kernel<<<n8x / 256, 256>>>(nullptr, 7, n8x);

    outproj_tf32_kernel<<<dim3(DMODEL / 128, MTOT / 128), 256, GEMM_SMEM>>>(bo, out);
}

// round 8
// speedup vs baseline: 7.3307x; 1.0815x over previous
#include <cuda_runtime.h>
#include <cuda_fp16.h>
#include <cstdint>

#define SLEN    2048
#define DMODEL  1024
#define NHEAD   16
#define DKH     64
#define NB      4
#define MTOT    (NB * SLEN)     // 8192

// ---------------- scratch (allocation-free: __device__ globals) ----------------
// pre-split fp16 hi/lo Q/K/V (Q pre-scaled by 0.125), layout [B,H,S,64]
__device__ __half g_Qh[(size_t)NB * NHEAD * SLEN * DKH];
__device__ __half g_Ql[(size_t)NB * NHEAD * SLEN * DKH];
__device__ __half g_Kh[(size_t)NB * NHEAD * SLEN * DKH];
__device__ __half g_Kl[(size_t)NB * NHEAD * SLEN * DKH];
__device__ __half g_Vh[(size_t)NB * NHEAD * SLEN * DKH];
__device__ __half g_Vl[(size_t)NB * NHEAD * SLEN * DKH];

// pre-converted tf32 operands, pair-permuted within each 8-k group:
// u32 order per group = [k0,k4,k1,k5,k2,k6,k3,k7]
__device__ uint32_t g_Xt[(size_t)3 * MTOT * DMODEL];     // q,k,v inputs
__device__ uint32_t g_Wt[(size_t)4 * DMODEL * DMODEL];   // wq,wk,wv,wo
__device__ uint32_t g_AOt[(size_t)MTOT * DMODEL];        // attn out, tf32 permuted

// ---------------- helpers ------------------------------------------------------
__device__ __forceinline__ uint32_t f2tf32(float f) {
    uint32_t u;
    asm("cvt.rna.tf32.f32 %0, %1;" : "=r"(u) : "f"(f));
    return u;
}

__device__ __forceinline__ void mma_tf32(float c[4], const uint32_t a[4], const uint32_t b[2]) {
    asm volatile(
        "mma.sync.aligned.m16n8k8.row.col.f32.tf32.tf32.f32 "
        "{%0,%1,%2,%3}, {%4,%5,%6,%7}, {%8,%9}, {%0,%1,%2,%3};"
        : "+f"(c[0]), "+f"(c[1]), "+f"(c[2]), "+f"(c[3])
        : "r"(a[0]), "r"(a[1]), "r"(a[2]), "r"(a[3]), "r"(b[0]), "r"(b[1]));
}

__device__ __forceinline__ uint32_t smem_u32(const void* p) {
    uint32_t a;
    asm("{ .reg .u64 t; cvta.to.shared.u64 t, %1; cvt.u32.u64 %0, t; }" : "=r"(a) : "l"(p));
    return a;
}

__device__ __forceinline__ void cp16(uint32_t dst, const void* src) {
    asm volatile("cp.async.cg.shared.global [%0], [%1], 16;" :: "r"(dst), "l"(src));
}
#define CP_COMMIT() asm volatile("cp.async.commit_group;")
#define CP_WAIT(n)  asm volatile("cp.async.wait_group %0;" :: "n"(n))

__device__ __forceinline__ uint2 ldsm_x2_trans(uint32_t addr) {
    uint2 r;
    asm volatile("ldmatrix.sync.aligned.m8n8.x2.trans.shared.b16 {%0,%1}, [%2];"
                 : "=r"(r.x), "=r"(r.y) : "r"(addr));
    return r;
}

// ---------------- tf32 pre-convert with pair permutation -----------------------
// sel: 0..2 = q/k/v -> g_Xt, 3..6 = wq/wk/wv/wo -> g_Wt
__global__ __launch_bounds__(256) void conv_tf32_kernel(const float* __restrict__ src,
                                                        int sel, int n8)
{
    int i = blockIdx.x * 256 + threadIdx.x;
    if (i >= n8) return;
    const float4* s = (const float4*)src;
    uint4* d;
    if (sel < 3) {
        d = (uint4*)(g_Xt + (size_t)sel * MTOT * DMODEL);
    } else {
        d = (uint4*)(g_Wt + (size_t)(sel - 3) * DMODEL * DMODEL);
    }
    float4 v0 = s[2 * i];
    float4 v1 = s[2 * i + 1];
    uint4 o0, o1;
    o0.x = f2tf32(v0.x); o0.y = f2tf32(v1.x);   // k0,k4
    o0.z = f2tf32(v0.y); o0.w = f2tf32(v1.y);   // k1,k5
    o1.x = f2tf32(v0.z); o1.y = f2tf32(v1.z);   // k2,k6
    o1.z = f2tf32(v0.w); o1.w = f2tf32(v1.w);   // k3,k7
    d[2 * i]     = o0;
    d[2 * i + 1] = o1;
}

// ======================= tf32 tensor-core GEMM =================================
#define BK2 32
#define P40 40
#define STAGEU (128 * P40)
#define GEMM_SMEM (2 * 2 * STAGEU * 4)        // 81920 bytes

__device__ __forceinline__ void gemm_tf32_main(const uint32_t* __restrict__ X,
                                               const uint32_t* __restrict__ W,
                                               int m0, int n0,
                                               float acc[4][4][4]) {
    extern __shared__ uint32_t su[];
    const int tid  = threadIdx.x;
    const int lane = tid & 31, warp = tid >> 5;
    const int wm = warp >> 2, wn = warp & 3;
    const int g  = lane >> 2, tg = lane & 3;

    const uint32_t sb = smem_u32(su);

#define ISSUE_TILE(kt, s)                                                           \
    do {                                                                            \
        uint32_t _b = sb + ((uint32_t)(s) * 2 * STAGEU) * 4u;                       \
        _Pragma("unroll")                                                           \
        for (int _j = 0; _j < 4; _j++) {                                            \
            int _seg = tid + _j * 256;                                              \
            int _row = _seg >> 3;                                                   \
            int _ch  = _seg & 7;                                                    \
            uint32_t _off = (uint32_t)(_row * P40 * 4 + _ch * 16);                  \
            cp16(_b + _off,                                                         \
                 (const char*)(X + (size_t)(m0 + _row) * DMODEL + (kt) * BK2) + _ch * 16); \
            cp16(_b + (uint32_t)(STAGEU * 4) + _off,                                \
                 (const char*)(W + (size_t)(n0 + _row) * DMODEL + (kt) * BK2) + _ch * 16); \
        }                                                                           \
    } while (0)

    const int NT = DMODEL / BK2;              // 32
    ISSUE_TILE(0, 0); CP_COMMIT();
    ISSUE_TILE(1, 1); CP_COMMIT();

    for (int kt = 0; kt < NT; kt++) {
        CP_WAIT(1);
        __syncthreads();

        const int s = kt & 1;
        const uint32_t* Asb = su + s * 2 * STAGEU;
        const uint32_t* Bsb = Asb + STAGEU;

#pragma unroll
        for (int kg = 0; kg < 4; kg++) {
            const int colb = kg * 8 + 2 * tg;
            uint32_t a[4][4], b[4][2];
#pragma unroll
            for (int fm = 0; fm < 4; fm++) {
                const int r = wm * 64 + fm * 16 + g;
                uint2 t0 = *(const uint2*)(Asb + r * P40 + colb);
                uint2 t1 = *(const uint2*)(Asb + (r + 8) * P40 + colb);
                a[fm][0] = t0.x; a[fm][2] = t0.y;
                a[fm][1] = t1.x; a[fm][3] = t1.y;
            }
#pragma unroll
            for (int fn = 0; fn < 4; fn++) {
                const int r = wn * 32 + fn * 8 + g;
                uint2 t = *(const uint2*)(Bsb + r * P40 + colb);
                b[fn][0] = t.x; b[fn][1] = t.y;
            }
#pragma unroll
            for (int fm = 0; fm < 4; fm++)
#pragma unroll
                for (int fn = 0; fn < 4; fn++)
                    mma_tf32(acc[fm][fn], a[fm], b[fn]);
        }

        __syncthreads();
        if (kt + 2 < NT) ISSUE_TILE(kt + 2, s);
        CP_COMMIT();
    }
#undef ISSUE_TILE
}

// ---------------- QKV projection -> pre-split fp16 hi/lo, head layout ----------
__global__ __launch_bounds__(256, 2) void qkv_tf32_kernel(
    const float* __restrict__ bq, const float* __restrict__ bk, const float* __restrict__ bv)
{
    const int z = blockIdx.z;
    const uint32_t* X = g_Xt + (size_t)z * MTOT * DMODEL;
    const uint32_t* W = g_Wt + (size_t)z * DMODEL * DMODEL;
    const float* Bb   = (z == 0) ? bq : (z == 1) ? bk : bv;
    __half* Hh        = (z == 0) ? g_Qh : (z == 1) ? g_Kh : g_Vh;
    __half* Hl        = (z == 0) ? g_Ql : (z == 1) ? g_Kl : g_Vl;
    const float scale = (z == 0) ? 0.125f : 1.0f;

    const int m0 = blockIdx.y * 128, n0 = blockIdx.x * 128;
    float acc[4][4][4];
#pragma unroll
    for (int i = 0; i < 4; i++)
#pragma unroll
        for (int j = 0; j < 4; j++)
#pragma unroll
            for (int t = 0; t < 4; t++) acc[i][j][t] = 0.f;

    gemm_tf32_main(X, W, m0, n0, acc);

    const int tid  = threadIdx.x;
    const int lane = tid & 31, warp = tid >> 5;
    const int wm = warp >> 2, wn = warp & 3;
    const int g  = lane >> 2, tg = lane & 3;

#pragma unroll
    for (int fn = 0; fn < 4; fn++) {
        const int n  = n0 + wn * 32 + fn * 8 + 2 * tg;
        const int hh = n >> 6, dd = n & 63;
        const float b0 = Bb[n], b1 = Bb[n + 1];
#pragma unroll
        for (int fm = 0; fm < 4; fm++) {
#pragma unroll
            for (int half_ = 0; half_ < 2; half_++) {
                const int m  = m0 + wm * 64 + fm * 16 + g + half_ * 8;
                const int bb = m >> 11;
                const int ss = m & (SLEN - 1);
                float v0 = (acc[fm][fn][half_ * 2 + 0] + b0) * scale;
                float v1 = (acc[fm][fn][half_ * 2 + 1] + b1) * scale;
                half2 hi = __floats2half2_rn(v0, v1);
                half2 lo = __floats2half2_rn(v0 - __low2float(hi), v1 - __high2float(hi));
                size_t idx = (((size_t)bb * NHEAD + hh) * SLEN + ss) * DKH + dd;
                *(half2*)(Hh + idx) = hi;
                *(half2*)(Hl + idx) = lo;
            }
        }
    }
}

// ---------------- output projection -------------------------------------------
__global__ __launch_bounds__(256, 2) void outproj_tf32_kernel(
    const float* __restrict__ Bb, float* __restrict__ Out)
{
    const uint32_t* W = g_Wt + (size_t)3 * DMODEL * DMODEL;
    const int m0 = blockIdx.y * 128, n0 = blockIdx.x * 128;
    float acc[4][4][4];
#pragma unroll
    for (int i = 0; i < 4; i++)
#pragma unroll
        for (int j = 0; j < 4; j++)
#pragma unroll
            for (int t = 0; t < 4; t++) acc[i][j][t] = 0.f;

    gemm_tf32_main(g_AOt, W, m0, n0, acc);

    const int tid  = threadIdx.x;
    const int lane = tid & 31, warp = tid >> 5;
    const int wm = warp >> 2, wn = warp & 3;
    const int g  = lane >> 2, tg = lane & 3;

#pragma unroll
    for (int fn = 0; fn < 4; fn++) {
        const int n = n0 + wn * 32 + fn * 8 + 2 * tg;
        const float b0 = Bb[n], b1 = Bb[n + 1];
#pragma unroll
        for (int fm = 0; fm < 4; fm++) {
#pragma unroll
            for (int half_ = 0; half_ < 2; half_++) {
                const int m = m0 + wm * 64 + fm * 16 + g + half_ * 8;
                *(float2*)(Out + (size_t)m * DMODEL + n) =
                    make_float2(acc[fm][fn][half_ * 2 + 0] + b0,
                                acc[fm][fn][half_ * 2 + 1] + b1);
            }
        }
    }
}

// ============ Flash attention: split-fp16 HMMA, cp.async loads =================
// smem (u32 units): Q hi/lo [128][36], K hi/lo [64][36], V hi/lo half[64][72],
// P hi/lo [128][36].
#define APITCH 36
#define OFF_QHI 0
#define OFF_QLO (OFF_QHI + 128 * APITCH)
#define OFF_KHI (OFF_QLO + 128 * APITCH)
#define OFF_KLO (OFF_KHI + 64 * APITCH)
#define OFF_VHI (OFF_KLO + 64 * APITCH)                 // half [64][72] = 2304 u32
#define OFF_VLO (OFF_VHI + 64 * APITCH)
#define OFF_PHI (OFF_VLO + 64 * APITCH)
#define OFF_PLO (OFF_PHI + 128 * APITCH)
#define ATTN_SMEM_U32 (OFF_PLO + 128 * APITCH)
#define ATTN_SMEM_BYTES (ATTN_SMEM_U32 * 4)             // 110592

__device__ __forceinline__ uint32_t h2u(half2 h) {
    return *reinterpret_cast<uint32_t*>(&h);
}

__device__ __forceinline__ void split_pack(float x, float y, uint32_t& hi, uint32_t& lo) {
    half2 h = __floats2half2_rn(x, y);
    float lx = x - __low2float(h);
    float ly = y - __high2float(h);
    half2 l = __floats2half2_rn(lx, ly);
    hi = h2u(h);
    lo = h2u(l);
}

__device__ __forceinline__ void mma_f16(float c[4], const uint32_t a[4],
                                        uint32_t b0, uint32_t b1) {
    asm volatile(
        "mma.sync.aligned.m16n8k16.row.col.f32.f16.f16.f32 "
        "{%0,%1,%2,%3}, {%4,%5,%6,%7}, {%8,%9}, {%0,%1,%2,%3};"
        : "+f"(c[0]), "+f"(c[1]), "+f"(c[2]), "+f"(c[3])
        : "r"(a[0]), "r"(a[1]), "r"(a[2]), "r"(a[3]), "r"(b0), "r"(b1));
}

__global__ __launch_bounds__(256, 2) void attn_hmma_kernel() {
    extern __shared__ uint32_t smu[];
    uint32_t* Qhi = smu + OFF_QHI;
    uint32_t* Qlo = smu + OFF_QLO;
    uint32_t* Khi = smu + OFF_KHI;
    uint32_t* Klo = smu + OFF_KLO;
    uint32_t* Phi = smu + OFF_PHI;
    uint32_t* Plo = smu + OFF_PLO;

    const int qb = 15 - blockIdx.x;            // long CTAs first
    const int bh = blockIdx.y;
    const size_t base = (size_t)bh * SLEN * DKH;
    const __half* Qhg = g_Qh + base;
    const __half* Qlg = g_Ql + base;
    const __half* Khg = g_Kh + base;
    const __half* Klg = g_Kl + base;
    const __half* Vhg = g_Vh + base;
    const __half* Vlg = g_Vl + base;

    const int tid  = threadIdx.x;
    const int lane = tid & 31, warp = tid >> 5;
    const int g  = lane >> 2, tg = lane & 3;
    const int row0 = warp * 16;
    const uint32_t sb = smem_u32(smu);

    // ---- load Q tile via cp.async (hi + lo) ----
#pragma unroll
    for (int j = 0; j < 8; j++) {
        int t   = tid + j * 256;       // 0..2047
        int row = t >> 4;              // 0..127
        int ch  = t & 15;              // 0..7 hi, 8..15 lo
        const __half* src = ((ch < 8) ? Qhg : Qlg) + (size_t)(qb * 128 + row) * DKH + (ch & 7) * 8;
        uint32_t off = (uint32_t)(((ch < 8) ? OFF_QHI : OFF_QLO) + row * APITCH + (ch & 7) * 4);
        cp16(sb + off * 4, src);
    }
    CP_COMMIT();

    float acc_o[8][4];
#pragma unroll
    for (int j = 0; j < 8; j++)
#pragma unroll
        for (int t = 0; t < 4; t++) acc_o[j][t] = 0.f;
    float m_run[2] = {-1.0e30f, -1.0e30f};
    float l_run[2] = {0.f, 0.f};

    const int ntiles = 2 * (qb + 1);
    for (int kb = 0; kb < ntiles; kb++) {
        __syncthreads();   // prior tile smem reads done

        // ---- load K + V tiles via cp.async ----
#pragma unroll
        for (int j = 0; j < 4; j++) {
            int t   = tid + j * 256;   // 0..1023
            int row = t >> 4;          // 0..63
            int ch  = t & 15;
            const __half* ks = ((ch < 8) ? Khg : Klg) + (size_t)(kb * 64 + row) * DKH + (ch & 7) * 8;
            uint32_t koff = (uint32_t)(((ch < 8) ? OFF_KHI : OFF_KLO) + row * APITCH + (ch & 7) * 4);
            cp16(sb + koff * 4, ks);
            const __half* vs = ((ch < 8) ? Vhg : Vlg) + (size_t)(kb * 64 + row) * DKH + (ch & 7) * 8;
            uint32_t voff = (uint32_t)(((ch < 8) ? OFF_VHI : OFF_VLO) + row * APITCH + (ch & 7) * 4);
            cp16(sb + voff * 4, vs);
        }
        CP_COMMIT();
        CP_WAIT(0);
        __syncthreads();

        const bool active = (kb * 64 <= qb * 128 + row0 + 15);

        if (active) {
            // ---- S = Q K^T (3-term split), 16 rows x 64 cols ----
            float s_acc[8][4];
#pragma unroll
            for (int j = 0; j < 8; j++)
#pragma unroll
                for (int t = 0; t < 4; t++) s_acc[j][t] = 0.f;

#pragma unroll
            for (int ks = 0; ks < 4; ks++) {
                uint32_t ahi[4], alo[4];
                {
                    int r0 = (row0 + g) * APITCH + ks * 8 + tg;
                    ahi[0] = Qhi[r0];
                    ahi[1] = Qhi[r0 + 8 * APITCH];
                    ahi[2] = Qhi[r0 + 4];
                    ahi[3] = Qhi[r0 + 8 * APITCH + 4];
                    alo[0] = Qlo[r0];
                    alo[1] = Qlo[r0 + 8 * APITCH];
                    alo[2] = Qlo[r0 + 4];
                    alo[3] = Qlo[r0 + 8 * APITCH + 4];
                }
#pragma unroll
                for (int fn = 0; fn < 8; fn++) {
                    int n0 = (fn * 8 + g) * APITCH + ks * 8 + tg;
                    uint32_t bh0 = Khi[n0], bh1 = Khi[n0 + 4];
                    uint32_t bl0 = Klo[n0], bl1 = Klo[n0 + 4];
                    mma_f16(s_acc[fn], ahi, bh0, bh1);
                    mma_f16(s_acc[fn], ahi, bl0, bl1);
                    mma_f16(s_acc[fn], alo, bh0, bh1);
                }
            }

            // ---- mask + online softmax + pack P ----
            const bool diag = (kb >= 2 * qb);
#pragma unroll
            for (int h = 0; h < 2; h++) {
                if (diag) {
                    int row = qb * 128 + row0 + g + 8 * h;
#pragma unroll
                    for (int fn = 0; fn < 8; fn++) {
                        int col = kb * 64 + fn * 8 + 2 * tg;
                        if (col > row)     s_acc[fn][h * 2 + 0] = -1.0e30f;
                        if (col + 1 > row) s_acc[fn][h * 2 + 1] = -1.0e30f;
                    }
                }
                float mx = s_acc[0][h * 2];
#pragma unroll
                for (int fn = 0; fn < 8; fn++) {
                    mx = fmaxf(mx, s_acc[fn][h * 2 + 0]);
                    mx = fmaxf(mx, s_acc[fn][h * 2 + 1]);
                }
                mx = fmaxf(mx, __shfl_xor_sync(0xffffffffu, mx, 1));
                mx = fmaxf(mx, __shfl_xor_sync(0xffffffffu, mx, 2));
                float mn   = fmaxf(m_run[h], mx);
                float corr = __expf(m_run[h] - mn);
                float rs = 0.f;
                float p[16];
#pragma unroll
                for (int fn = 0; fn < 8; fn++) {
                    p[fn * 2 + 0] = __expf(s_acc[fn][h * 2 + 0] - mn);
                    p[fn * 2 + 1] = __expf(s_acc[fn][h * 2 + 1] - mn);
                    rs += p[fn * 2 + 0] + p[fn * 2 + 1];
                }
                rs += __shfl_xor_sync(0xffffffffu, rs, 1);
                rs += __shfl_xor_sync(0xffffffffu, rs, 2);
                l_run[h] = l_run[h] * corr + rs;
                m_run[h] = mn;
#pragma unroll
                for (int fn = 0; fn < 8; fn++) {
                    acc_o[fn][h * 2 + 0] *= corr;
                    acc_o[fn][h * 2 + 1] *= corr;
                }
                int row_l = row0 + g + 8 * h;
#pragma unroll
                for (int fn = 0; fn < 8; fn++) {
                    uint32_t hi, lo;
                    split_pack(p[fn * 2 + 0], p[fn * 2 + 1], hi, lo);
                    int kc = row_l * APITCH + fn * 4 + tg;
                    Phi[kc] = hi;
                    Plo[kc] = lo;
                }
            }

            // ---- O += P V; V B-fragments via ldmatrix.x2.trans ----
            __syncwarp();   // P rows are warp-private
#pragma unroll
            for (int ks = 0; ks < 4; ks++) {
                uint32_t ahi[4], alo[4];
                {
                    int r0 = (row0 + g) * APITCH + ks * 8 + tg;
                    ahi[0] = Phi[r0];
                    ahi[1] = Phi[r0 + 8 * APITCH];
                    ahi[2] = Phi[r0 + 4];
                    ahi[3] = Phi[r0 + 8 * APITCH + 4];
                    alo[0] = Plo[r0];
                    alo[1] = Plo[r0 + 8 * APITCH];
                    alo[2] = Plo[r0 + 4];
                    alo[3] = Plo[r0 + 8 * APITCH + 4];
                }
                const int vrow = ks * 16 + (lane & 15);
                const uint32_t abH = sb + (uint32_t)(OFF_VHI + vrow * APITCH) * 4;
                const uint32_t abL = sb + (uint32_t)(OFF_VLO + vrow * APITCH) * 4;
#pragma unroll
                for (int fn = 0; fn < 8; fn++) {
                    uint2 bh = ldsm_x2_trans(abH + fn * 16);
                    uint2 bl = ldsm_x2_trans(abL + fn * 16);
                    mma_f16(acc_o[fn], ahi, bh.x, bh.y);
                    mma_f16(acc_o[fn], ahi, bl.x, bl.y);
                    mma_f16(acc_o[fn], alo, bh.x, bh.y);
                }
            }
        }
    }

    // ---- normalize + write tf32 pair-permuted AO directly ----
    const int bb = bh >> 4, hh = bh & 15;
    const int kk0 = 2 * tg, kk1 = 2 * tg + 1;
    const int p0 = ((kk0 & 3) << 1) | (kk0 >> 2);
    const int p1 = ((kk1 & 3) << 1) | (kk1 >> 2);
#pragma unroll
    for (int h = 0; h < 2; h++) {
        float invl = 1.0f / l_run[h];
        int row = qb * 128 + row0 + g + 8 * h;
        uint32_t* dst = g_AOt + ((size_t)bb * SLEN + row) * DMODEL + hh * DKH;
#pragma unroll
        for (int fn = 0; fn < 8; fn++) {
            dst[fn * 8 + p0] = f2tf32(acc_o[fn][h * 2 + 0] * invl);
            dst[fn * 8 + p1] = f2tf32(acc_o[fn][h * 2 + 1] * invl);
        }
    }
}

// ---------------- launch -------------------------------------------------------
extern "C" void kernel_launch(void* const* d_in, const int* in_sizes, int n_in,
                              void* d_out, int out_size) {
    const float* q  = (const float*)d_in[0];
    const float* k  = (const float*)d_in[1];
    const float* v  = (const float*)d_in[2];
    // d_in[3] = mask (int32 tril) — causal, applied analytically
    const float* wq = (const float*)d_in[4];
    const float* bq = (const float*)d_in[5];
    const float* wk = (const float*)d_in[6];
    const float* bk = (const float*)d_in[7];
    const float* wv = (const float*)d_in[8];
    const float* bv = (const float*)d_in[9];
    const float* wo = (const float*)d_in[10];
    const float* bo = (const float*)d_in[11];
    float* out = (float*)d_out;

    cudaFuncSetAttribute(qkv_tf32_kernel, cudaFuncAttributeMaxDynamicSharedMemorySize, GEMM_SMEM);
    cudaFuncSetAttribute(outproj_tf32_kernel, cudaFuncAttributeMaxDynamicSharedMemorySize, GEMM_SMEM);
    cudaFuncSetAttribute(attn_hmma_kernel, cudaFuncAttributeMaxDynamicSharedMemorySize, ATTN_SMEM_BYTES);

    const int n8x = MTOT * DMODEL / 8;       // 1048576
    const int n8w = DMODEL * DMODEL / 8;     // 131072
    conv_tf32_kernel<<<n8x / 256, 256>>>(q,  0, n8x);
    conv_tf32_kernel<<<n8x / 256, 256>>>(k,  1, n8x);
    conv_tf32_kernel<<<n8x / 256, 256>>>(v,  2, n8x);
    conv_tf32_kernel<<<n8w / 256, 256>>>(wq, 3, n8w);
    conv_tf32_kernel<<<n8w / 256, 256>>>(wk, 4, n8w);
    conv_tf32_kernel<<<n8w / 256, 256>>>(wv, 5, n8w);
    conv_tf32_kernel<<<n8w / 256, 256>>>(wo, 6, n8w);

    qkv_tf32_kernel<<<dim3(DMODEL / 128, MTOT / 128, 3), 256, GEMM_SMEM>>>(bq, bk, bv);

    attn_hmma_kernel<<<dim3(SLEN / 128, NB * NHEAD), 256, ATTN_SMEM_BYTES>>>();

    outproj_tf32_kernel<<<dim3(DMODEL / 128, MTOT / 128), 256, GEMM_SMEM>>>(bo, out);
}

// round 9
// speedup vs baseline: 7.6283x; 1.0406x over previous
#include <cuda_runtime.h>
#include <cuda_fp16.h>
#include <cstdint>

#define SLEN    2048
#define DMODEL  1024
#define NHEAD   16
#define DKH     64
#define NB      4
#define MTOT    (NB * SLEN)     // 8192

// ---------------- scratch (allocation-free: __device__ globals) ----------------
// pre-split fp16 hi/lo Q/K/V, layout [B,H,S,64].
// Q is pre-scaled by 0.125*log2(e); Q and K are d-PAIR-PERMUTED (per 8-u32 group
// order [p0,p4,p1,p5,p2,p6,p3,p7]); V is natural.
__device__ __half g_Qh[(size_t)NB * NHEAD * SLEN * DKH];
__device__ __half g_Ql[(size_t)NB * NHEAD * SLEN * DKH];
__device__ __half g_Kh[(size_t)NB * NHEAD * SLEN * DKH];
__device__ __half g_Kl[(size_t)NB * NHEAD * SLEN * DKH];
__device__ __half g_Vh[(size_t)NB * NHEAD * SLEN * DKH];
__device__ __half g_Vl[(size_t)NB * NHEAD * SLEN * DKH];

// pre-converted tf32 operands, pair-permuted within each 8-k group
__device__ uint32_t g_Xt[(size_t)3 * MTOT * DMODEL];     // q,k,v inputs
__device__ uint32_t g_Wt[(size_t)4 * DMODEL * DMODEL];   // wq,wk,wv,wo
__device__ uint32_t g_AOt[(size_t)MTOT * DMODEL];        // attn out, tf32 permuted

// ---------------- helpers ------------------------------------------------------
__device__ __forceinline__ uint32_t f2tf32(float f) {
    uint32_t u;
    asm("cvt.rna.tf32.f32 %0, %1;" : "=r"(u) : "f"(f));
    return u;
}

__device__ __forceinline__ void mma_tf32(float c[4], const uint32_t a[4], const uint32_t b[2]) {
    asm volatile(
        "mma.sync.aligned.m16n8k8.row.col.f32.tf32.tf32.f32 "
        "{%0,%1,%2,%3}, {%4,%5,%6,%7}, {%8,%9}, {%0,%1,%2,%3};"
        : "+f"(c[0]), "+f"(c[1]), "+f"(c[2]), "+f"(c[3])
        : "r"(a[0]), "r"(a[1]), "r"(a[2]), "r"(a[3]), "r"(b[0]), "r"(b[1]));
}

__device__ __forceinline__ uint32_t smem_u32(const void* p) {
    uint32_t a;
    asm("{ .reg .u64 t; cvta.to.shared.u64 t, %1; cvt.u32.u64 %0, t; }" : "=r"(a) : "l"(p));
    return a;
}

__device__ __forceinline__ void cp16(uint32_t dst, const void* src) {
    asm volatile("cp.async.cg.shared.global [%0], [%1], 16;" :: "r"(dst), "l"(src));
}
#define CP_COMMIT() asm volatile("cp.async.commit_group;")
#define CP_WAIT(n)  asm volatile("cp.async.wait_group %0;" :: "n"(n))

__device__ __forceinline__ uint2 ldsm_x2_trans(uint32_t addr) {
    uint2 r;
    asm volatile("ldmatrix.sync.aligned.m8n8.x2.trans.shared.b16 {%0,%1}, [%2];"
                 : "=r"(r.x), "=r"(r.y) : "r"(addr));
    return r;
}

// ---------------- fused tf32 pre-convert (all 7 tensors, one launch) -----------
__global__ __launch_bounds__(256) void conv_all_kernel(
    const float* __restrict__ q, const float* __restrict__ k, const float* __restrict__ v,
    const float* __restrict__ wq, const float* __restrict__ wk,
    const float* __restrict__ wv, const float* __restrict__ wo)
{
    int b = blockIdx.x;
    const float* src;
    uint32_t* dst;
    int i;
    if (b < 12288) {
        int sel = b >> 12;
        src = (sel == 0) ? q : (sel == 1) ? k : v;
        dst = g_Xt + (size_t)sel * MTOT * DMODEL;
        i = (b & 4095) * 256 + threadIdx.x;
    } else {
        int sel = (b - 12288) >> 9;
        src = (sel == 0) ? wq : (sel == 1) ? wk : (sel == 2) ? wv : wo;
        dst = g_Wt + (size_t)sel * DMODEL * DMODEL;
        i = ((b - 12288) & 511) * 256 + threadIdx.x;
    }
    const float4* s4 = (const float4*)src;
    uint4* d4 = (uint4*)dst;
    float4 v0 = s4[2 * i];
    float4 v1 = s4[2 * i + 1];
    uint4 o0, o1;
    o0.x = f2tf32(v0.x); o0.y = f2tf32(v1.x);
    o0.z = f2tf32(v0.y); o0.w = f2tf32(v1.y);
    o1.x = f2tf32(v0.z); o1.y = f2tf32(v1.z);
    o1.z = f2tf32(v0.w); o1.w = f2tf32(v1.w);
    d4[2 * i]     = o0;
    d4[2 * i + 1] = o1;
}

// ======================= tf32 tensor-core GEMM =================================
#define BK2 32
#define P40 40
#define STAGEU (128 * P40)
#define GEMM_SMEM (2 * 2 * STAGEU * 4)        // 81920 bytes

__device__ __forceinline__ void gemm_tf32_main(const uint32_t* __restrict__ X,
                                               const uint32_t* __restrict__ W,
                                               int m0, int n0,
                                               float acc[4][4][4]) {
    extern __shared__ uint32_t su[];
    const int tid  = threadIdx.x;
    const int lane = tid & 31, warp = tid >> 5;
    const int wm = warp >> 2, wn = warp & 3;
    const int g  = lane >> 2, tg = lane & 3;

    const uint32_t sb = smem_u32(su);

#define ISSUE_TILE(kt, s)                                                           \
    do {                                                                            \
        uint32_t _b = sb + ((uint32_t)(s) * 2 * STAGEU) * 4u;                       \
        _Pragma("unroll")                                                           \
        for (int _j = 0; _j < 4; _j++) {                                            \
            int _seg = tid + _j * 256;                                              \
            int _row = _seg >> 3;                                                   \
            int _ch  = _seg & 7;                                                    \
            uint32_t _off = (uint32_t)(_row * P40 * 4 + _ch * 16);                  \
            cp16(_b + _off,                                                         \
                 (const char*)(X + (size_t)(m0 + _row) * DMODEL + (kt) * BK2) + _ch * 16); \
            cp16(_b + (uint32_t)(STAGEU * 4) + _off,                                \
                 (const char*)(W + (size_t)(n0 + _row) * DMODEL + (kt) * BK2) + _ch * 16); \
        }                                                                           \
    } while (0)

    const int NT = DMODEL / BK2;              // 32
    ISSUE_TILE(0, 0); CP_COMMIT();
    ISSUE_TILE(1, 1); CP_COMMIT();

    for (int kt = 0; kt < NT; kt++) {
        CP_WAIT(1);
        __syncthreads();

        const int s = kt & 1;
        const uint32_t* Asb = su + s * 2 * STAGEU;
        const uint32_t* Bsb = Asb + STAGEU;

#pragma unroll
        for (int kg = 0; kg < 4; kg++) {
            const int colb = kg * 8 + 2 * tg;
            uint32_t a[4][4], b[4][2];
#pragma unroll
            for (int fm = 0; fm < 4; fm++) {
                const int r = wm * 64 + fm * 16 + g;
                uint2 t0 = *(const uint2*)(Asb + r * P40 + colb);
                uint2 t1 = *(const uint2*)(Asb + (r + 8) * P40 + colb);
                a[fm][0] = t0.x; a[fm][2] = t0.y;
                a[fm][1] = t1.x; a[fm][3] = t1.y;
            }
#pragma unroll
            for (int fn = 0; fn < 4; fn++) {
                const int r = wn * 32 + fn * 8 + g;
                uint2 t = *(const uint2*)(Bsb + r * P40 + colb);
                b[fn][0] = t.x; b[fn][1] = t.y;
            }
#pragma unroll
            for (int fm = 0; fm < 4; fm++)
#pragma unroll
                for (int fn = 0; fn < 4; fn++)
                    mma_tf32(acc[fm][fn], a[fm], b[fn]);
        }

        __syncthreads();
        if (kt + 2 < NT) ISSUE_TILE(kt + 2, s);
        CP_COMMIT();
    }
#undef ISSUE_TILE
}

// ---------------- QKV projection -> pre-split fp16 hi/lo -----------------------
// Q scaled by 0.125*log2e; Q,K written d-pair-permuted; V natural.
#define QSCALE 0.180336880f

__global__ __launch_bounds__(256, 2) void qkv_tf32_kernel(
    const float* __restrict__ bq, const float* __restrict__ bk, const float* __restrict__ bv)
{
    const int z = blockIdx.z;
    const uint32_t* X = g_Xt + (size_t)z * MTOT * DMODEL;
    const uint32_t* W = g_Wt + (size_t)z * DMODEL * DMODEL;
    const float* Bb   = (z == 0) ? bq : (z == 1) ? bk : bv;
    __half* Hh        = (z == 0) ? g_Qh : (z == 1) ? g_Kh : g_Vh;
    __half* Hl        = (z == 0) ? g_Ql : (z == 1) ? g_Kl : g_Vl;
    const float scale = (z == 0) ? QSCALE : 1.0f;

    const int m0 = blockIdx.y * 128, n0 = blockIdx.x * 128;
    float acc[4][4][4];
#pragma unroll
    for (int i = 0; i < 4; i++)
#pragma unroll
        for (int j = 0; j < 4; j++)
#pragma unroll
            for (int t = 0; t < 4; t++) acc[i][j][t] = 0.f;

    gemm_tf32_main(X, W, m0, n0, acc);

    const int tid  = threadIdx.x;
    const int lane = tid & 31, warp = tid >> 5;
    const int wm = warp >> 2, wn = warp & 3;
    const int g  = lane >> 2, tg = lane & 3;

#pragma unroll
    for (int fn = 0; fn < 4; fn++) {
        const int n  = n0 + wn * 32 + fn * 8 + 2 * tg;
        const int hh = n >> 6, dd = n & 63;
        // pair-permuted d position for Q/K; natural for V
        int ddw;
        if (z < 2) {
            int kk  = dd >> 1;
            int grp = kk >> 3, pig = kk & 7;
            int pp  = ((pig & 3) << 1) | (pig >> 2);
            ddw = (grp * 8 + pp) * 2;
        } else {
            ddw = dd;
        }
        const float b0 = Bb[n], b1 = Bb[n + 1];
#pragma unroll
        for (int fm = 0; fm < 4; fm++) {
#pragma unroll
            for (int half_ = 0; half_ < 2; half_++) {
                const int m  = m0 + wm * 64 + fm * 16 + g + half_ * 8;
                const int bb = m >> 11;
                const int ss = m & (SLEN - 1);
                float v0 = (acc[fm][fn][half_ * 2 + 0] + b0) * scale;
                float v1 = (acc[fm][fn][half_ * 2 + 1] + b1) * scale;
                half2 hi = __floats2half2_rn(v0, v1);
                half2 lo = __floats2half2_rn(v0 - __low2float(hi), v1 - __high2float(hi));
                size_t idx = (((size_t)bb * NHEAD + hh) * SLEN + ss) * DKH + ddw;
                *(half2*)(Hh + idx) = hi;
                *(half2*)(Hl + idx) = lo;
            }
        }
    }
}

// ---------------- output projection -------------------------------------------
__global__ __launch_bounds__(256, 2) void outproj_tf32_kernel(
    const float* __restrict__ Bb, float* __restrict__ Out)
{
    const uint32_t* W = g_Wt + (size_t)3 * DMODEL * DMODEL;
    const int m0 = blockIdx.y * 128, n0 = blockIdx.x * 128;
    float acc[4][4][4];
#pragma unroll
    for (int i = 0; i < 4; i++)
#pragma unroll
        for (int j = 0; j < 4; j++)
#pragma unroll
            for (int t = 0; t < 4; t++) acc[i][j][t] = 0.f;

    gemm_tf32_main(g_AOt, W, m0, n0, acc);

    const int tid  = threadIdx.x;
    const int lane = tid & 31, warp = tid >> 5;
    const int wm = warp >> 2, wn = warp & 3;
    const int g  = lane >> 2, tg = lane & 3;

#pragma unroll
    for (int fn = 0; fn < 4; fn++) {
        const int n = n0 + wn * 32 + fn * 8 + 2 * tg;
        const float b0 = Bb[n], b1 = Bb[n + 1];
#pragma unroll
        for (int fm = 0; fm < 4; fm++) {
#pragma unroll
            for (int half_ = 0; half_ < 2; half_++) {
                const int m = m0 + wm * 64 + fm * 16 + g + half_ * 8;
                *(float2*)(Out + (size_t)m * DMODEL + n) =
                    make_float2(acc[fm][fn][half_ * 2 + 0] + b0,
                                acc[fm][fn][half_ * 2 + 1] + b1);
            }
        }
    }
}

// ============ Flash attention: split-fp16 HMMA, Q+P in registers ===============
// smem: 2 stages of { K hi/lo [64][40], V hi/lo [64][36] } (u32 units).
#define KPITCH 40
#define VPITCH 36
#define ST_KHI 0
#define ST_KLO 2560
#define ST_VHI 5120
#define ST_VLO 7424
#define STAGE_U 9728
#define ATTN_SMEM_BYTES (2 * STAGE_U * 4)     // 77824

__device__ __forceinline__ uint32_t h2u(half2 h) {
    return *reinterpret_cast<uint32_t*>(&h);
}

__device__ __forceinline__ void split_pack(float x, float y, uint32_t& hi, uint32_t& lo) {
    half2 h = __floats2half2_rn(x, y);
    float lx = x - __low2float(h);
    float ly = y - __high2float(h);
    half2 l = __floats2half2_rn(lx, ly);
    hi = h2u(h);
    lo = h2u(l);
}

__device__ __forceinline__ void mma_f16(float c[4], const uint32_t a[4],
                                        uint32_t b0, uint32_t b1) {
    asm volatile(
        "mma.sync.aligned.m16n8k16.row.col.f32.f16.f16.f32 "
        "{%0,%1,%2,%3}, {%4,%5,%6,%7}, {%8,%9}, {%0,%1,%2,%3};"
        : "+f"(c[0]), "+f"(c[1]), "+f"(c[2]), "+f"(c[3])
        : "r"(a[0]), "r"(a[1]), "r"(a[2]), "r"(a[3]), "r"(b0), "r"(b1));
}

__global__ __launch_bounds__(256, 2) void attn_hmma_kernel() {
    extern __shared__ uint32_t smu[];

    const int qb = 15 - blockIdx.x;            // long CTAs first
    const int bh = blockIdx.y;
    const size_t base = (size_t)bh * SLEN * DKH;
    const __half* Khg = g_Kh + base;
    const __half* Klg = g_Kl + base;
    const __half* Vhg = g_Vh + base;
    const __half* Vlg = g_Vl + base;

    const int tid  = threadIdx.x;
    const int lane = tid & 31, warp = tid >> 5;
    const int g  = lane >> 2, tg = lane & 3;
    const int row0 = warp * 16;
    const uint32_t sb = smem_u32(smu);

#define ATTN_ISSUE(kb_, s_)                                                         \
    do {                                                                            \
        _Pragma("unroll")                                                           \
        for (int _j = 0; _j < 4; _j++) {                                            \
            int _t = tid + _j * 256;                                                \
            int _row = _t >> 4;                                                     \
            int _ch = _t & 15;                                                      \
            int _c7 = _ch & 7;                                                      \
            const __half* _ks = ((_ch < 8) ? Khg : Klg)                             \
                                + (size_t)((kb_) * 64 + _row) * DKH + _c7 * 8;      \
            cp16(sb + (uint32_t)((s_) * STAGE_U + ((_ch < 8) ? ST_KHI : ST_KLO)     \
                                  + _row * KPITCH + _c7 * 4) * 4, _ks);             \
            const __half* _vs = ((_ch < 8) ? Vhg : Vlg)                             \
                                + (size_t)((kb_) * 64 + _row) * DKH + _c7 * 8;      \
            cp16(sb + (uint32_t)((s_) * STAGE_U + ((_ch < 8) ? ST_VHI : ST_VLO)     \
                                  + _row * VPITCH + _c7 * 4) * 4, _vs);             \
        }                                                                           \
    } while (0)

    ATTN_ISSUE(0, 0); CP_COMMIT();
    ATTN_ISSUE(1, 1); CP_COMMIT();

    // ---- Q fragments -> registers (pair-permuted global, LDG.64) ----
    uint32_t qh[4][4], ql[4][4];
    {
        const uint32_t* Qg  = (const uint32_t*)g_Qh + (base >> 1)
                              + (size_t)(qb * 128 + row0 + g) * 32;
        const uint32_t* Qgl = (const uint32_t*)g_Ql + (base >> 1)
                              + (size_t)(qb * 128 + row0 + g) * 32;
#pragma unroll
        for (int ks = 0; ks < 4; ks++) {
            uint2 a0 = *(const uint2*)(Qg + ks * 8 + 2 * tg);
            uint2 a1 = *(const uint2*)(Qg + 8 * 32 + ks * 8 + 2 * tg);
            qh[ks][0] = a0.x; qh[ks][1] = a1.x; qh[ks][2] = a0.y; qh[ks][3] = a1.y;
            uint2 b0 = *(const uint2*)(Qgl + ks * 8 + 2 * tg);
            uint2 b1 = *(const uint2*)(Qgl + 8 * 32 + ks * 8 + 2 * tg);
            ql[ks][0] = b0.x; ql[ks][1] = b1.x; ql[ks][2] = b0.y; ql[ks][3] = b1.y;
        }
    }

    float acc_o[8][4];
#pragma unroll
    for (int j = 0; j < 8; j++)
#pragma unroll
        for (int t = 0; t < 4; t++) acc_o[j][t] = 0.f;
    float m_run[2] = {-1.0e30f, -1.0e30f};
    float l_run[2] = {0.f, 0.f};

    const int ntiles = 2 * (qb + 1);
    for (int kb = 0; kb < ntiles; kb++) {
        CP_WAIT(1);
        __syncthreads();

        const int s = kb & 1;
        const uint32_t* Khi_s = smu + s * STAGE_U + ST_KHI;
        const uint32_t* Klo_s = smu + s * STAGE_U + ST_KLO;
        const uint32_t vhiB = sb + (uint32_t)(s * STAGE_U + ST_VHI) * 4;
        const uint32_t vloB = sb + (uint32_t)(s * STAGE_U + ST_VLO) * 4;

        const bool active = (kb * 64 <= qb * 128 + row0 + 15);

        if (active) {
            // ---- S = Q K^T (3-term split) ----
            float s_acc[8][4];
#pragma unroll
            for (int j = 0; j < 8; j++)
#pragma unroll
                for (int t = 0; t < 4; t++) s_acc[j][t] = 0.f;

#pragma unroll
            for (int ks = 0; ks < 4; ks++) {
#pragma unroll
                for (int fn = 0; fn < 8; fn++) {
                    const int o = (fn * 8 + g) * KPITCH + ks * 8 + 2 * tg;
                    uint2 bh = *(const uint2*)(Khi_s + o);
                    uint2 bl = *(const uint2*)(Klo_s + o);
                    mma_f16(s_acc[fn], qh[ks], bh.x, bh.y);
                    mma_f16(s_acc[fn], qh[ks], bl.x, bl.y);
                    mma_f16(s_acc[fn], ql[ks], bh.x, bh.y);
                }
            }

            // ---- mask + online softmax (base-2) + pack P into registers ----
            uint32_t php[8][2], plp[8][2];
            const bool diag = (kb >= 2 * qb);
#pragma unroll
            for (int h = 0; h < 2; h++) {
                if (diag) {
                    int row = qb * 128 + row0 + g + 8 * h;
#pragma unroll
                    for (int fn = 0; fn < 8; fn++) {
                        int col = kb * 64 + fn * 8 + 2 * tg;
                        if (col > row)     s_acc[fn][h * 2 + 0] = -1.0e30f;
                        if (col + 1 > row) s_acc[fn][h * 2 + 1] = -1.0e30f;
                    }
                }
                float mx = s_acc[0][h * 2];
#pragma unroll
                for (int fn = 0; fn < 8; fn++) {
                    mx = fmaxf(mx, s_acc[fn][h * 2 + 0]);
                    mx = fmaxf(mx, s_acc[fn][h * 2 + 1]);
                }
                mx = fmaxf(mx, __shfl_xor_sync(0xffffffffu, mx, 1));
                mx = fmaxf(mx, __shfl_xor_sync(0xffffffffu, mx, 2));
                float mn   = fmaxf(m_run[h], mx);
                float corr = exp2f(m_run[h] - mn);
                float rs = 0.f;
#pragma unroll
                for (int fn = 0; fn < 8; fn++) {
                    float p0 = exp2f(s_acc[fn][h * 2 + 0] - mn);
                    float p1 = exp2f(s_acc[fn][h * 2 + 1] - mn);
                    rs += p0 + p1;
                    split_pack(p0, p1, php[fn][h], plp[fn][h]);
                }
                rs += __shfl_xor_sync(0xffffffffu, rs, 1);
                rs += __shfl_xor_sync(0xffffffffu, rs, 2);
                l_run[h] = l_run[h] * corr + rs;
                m_run[h] = mn;
#pragma unroll
                for (int fn = 0; fn < 8; fn++) {
                    acc_o[fn][h * 2 + 0] *= corr;
                    acc_o[fn][h * 2 + 1] *= corr;
                }
            }

            // ---- O += P V (P fragments are thread-local registers) ----
#pragma unroll
            for (int ks = 0; ks < 4; ks++) {
                uint32_t ahi[4] = { php[2 * ks][0], php[2 * ks][1],
                                    php[2 * ks + 1][0], php[2 * ks + 1][1] };
                uint32_t alo[4] = { plp[2 * ks][0], plp[2 * ks][1],
                                    plp[2 * ks + 1][0], plp[2 * ks + 1][1] };
                const int vrow = ks * 16 + (lane & 15);
                const uint32_t abH = vhiB + (uint32_t)(vrow * VPITCH) * 4;
                const uint32_t abL = vloB + (uint32_t)(vrow * VPITCH) * 4;
#pragma unroll
                for (int fn = 0; fn < 8; fn++) {
                    uint2 bh = ldsm_x2_trans(abH + fn * 16);
                    uint2 bl = ldsm_x2_trans(abL + fn * 16);
                    mma_f16(acc_o[fn], ahi, bh.x, bh.y);
                    mma_f16(acc_o[fn], ahi, bl.x, bl.y);
                    mma_f16(acc_o[fn], alo, bh.x, bh.y);
                }
            }
        }

        __syncthreads();
        if (kb + 2 < ntiles) ATTN_ISSUE(kb + 2, s);
        CP_COMMIT();
    }
#undef ATTN_ISSUE

    // ---- normalize + write tf32 pair-permuted AO directly ----
    const int bb = bh >> 4, hh = bh & 15;
    const int kk0 = 2 * tg, kk1 = 2 * tg + 1;
    const int p0 = ((kk0 & 3) << 1) | (kk0 >> 2);
    const int p1 = ((kk1 & 3) << 1) | (kk1 >> 2);
#pragma unroll
    for (int h = 0; h < 2; h++) {
        float invl = 1.0f / l_run[h];
        int row = qb * 128 + row0 + g + 8 * h;
        uint32_t* dst = g_AOt + ((size_t)bb * SLEN + row) * DMODEL + hh * DKH;
#pragma unroll
        for (int fn = 0; fn < 8; fn++) {
            dst[fn * 8 + p0] = f2tf32(acc_o[fn][h * 2 + 0] * invl);
            dst[fn * 8 + p1] = f2tf32(acc_o[fn][h * 2 + 1] * invl);
        }
    }
}

// ---------------- launch -------------------------------------------------------
extern "C" void kernel_launch(void* const* d_in, const int* in_sizes, int n_in,
                              void* d_out, int out_size) {
    const float* q  = (const float*)d_in[0];
    const float* k  = (const float*)d_in[1];
    const float* v  = (const float*)d_in[2];
    // d_in[3] = mask (int32 tril) — causal, applied analytically
    const float* wq = (const float*)d_in[4];
    const float* bq = (const float*)d_in[5];
    const float* wk = (const float*)d_in[6];
    const float* bk = (const float*)d_in[7];
    const float* wv = (const float*)d_in[8];
    const float* bv = (const float*)d_in[9];
    const float* wo = (const float*)d_in[10];
    const float* bo = (const float*)d_in[11];
    float* out = (float*)d_out;

    cudaFuncSetAttribute(qkv_tf32_kernel, cudaFuncAttributeMaxDynamicSharedMemorySize, GEMM_SMEM);
    cudaFuncSetAttribute(outproj_tf32_kernel, cudaFuncAttributeMaxDynamicSharedMemorySize, GEMM_SMEM);
    cudaFuncSetAttribute(attn_hmma_kernel, cudaFuncAttributeMaxDynamicSharedMemorySize, ATTN_SMEM_BYTES);

    conv_all_kernel<<<14336, 256>>>(q, k, v, wq, wk, wv, wo);

    qkv_tf32_kernel<<<dim3(DMODEL / 128, MTOT / 128, 3), 256, GEMM_SMEM>>>(bq, bk, bv);

    attn_hmma_kernel<<<dim3(SLEN / 128, NB * NHEAD), 256, ATTN_SMEM_BYTES>>>();

    outproj_tf32_kernel<<<dim3(DMODEL / 128, MTOT / 128), 256, GEMM_SMEM>>>(bo, out);
}